// round 2
// baseline (speedup 1.0000x reference)
#include <cuda_runtime.h>
#include <math.h>

#define B_ 32
#define NN 511
#define F_ 512
#define F3 1536

// ---------------- scratch (static device globals; no runtime alloc) ----------------
static __device__ __align__(16) float g_enode[B_ * F_];
static __device__ __align__(16) float g_eforw[B_ * F_];
static __device__ __align__(16) float g_scores[B_ * 512];
static __device__ __align__(16) float g_feat2[(size_t)B_ * NN * F_];
static __device__ __align__(16) float g_fe_iou[(size_t)B_ * NN * F3];
static __device__ __align__(16) float g_ff[(size_t)B_ * 255 * F_];
static __device__ __align__(16) float g_h[(size_t)B_ * NN * F_];
static __device__ __align__(16) float g_c[(size_t)B_ * NN * F_];
static __device__ __align__(16) float g_fc[(size_t)B_ * 256 * F_];
static __device__ __align__(16) float g_iou[(size_t)B_ * 128 * F3];
static __device__ __align__(16) float g_r[B_ * 512];

__device__ __forceinline__ float sigf(float x) { return 1.f / (1.f + expf(-x)); }

// ---------------- e_node / e_forw ----------------
__global__ void enode_k(const float* __restrict__ eh,
                        const float* __restrict__ Wn,
                        const float* __restrict__ Wf) {
    int warp = threadIdx.x >> 5, lane = threadIdx.x & 31;
    int j = blockIdx.x * 8 + warp;
    int b = blockIdx.y;
    const float* W = blockIdx.z ? Wf : Wn;
    float* o = blockIdx.z ? g_eforw : g_enode;
    const float4* wr = (const float4*)(W + (size_t)j * 1024);
    const float4* er = (const float4*)(eh + (size_t)b * 1024);
    float s = 0.f;
    for (int t = lane; t < 256; t += 32) {
        float4 w = wr[t], e = er[t];
        s += w.x * e.x + w.y * e.y + w.z * e.z + w.w * e.w;
    }
    #pragma unroll
    for (int off = 16; off; off >>= 1) s += __shfl_xor_sync(0xffffffffu, s, off);
    if (!lane) o[b * F_ + j] = s;
}

// ---------------- scores ----------------
__global__ void scores_k(const float* __restrict__ feat) {
    int gw = (blockIdx.x * blockDim.x + threadIdx.x) >> 5;
    int lane = threadIdx.x & 31;
    if (gw >= B_ * NN) return;
    int b = gw / NN;
    const float4* fr = (const float4*)(feat + (size_t)gw * F_);
    const float4* er = (const float4*)(g_enode + b * F_);
    float s = 0.f;
    for (int t = lane; t < 128; t += 32) {
        float4 f = fr[t], e = er[t];
        s += f.x * e.x + f.y * e.y + f.z * e.z + f.w * e.w;
    }
    #pragma unroll
    for (int off = 16; off; off >>= 1) s += __shfl_xor_sync(0xffffffffu, s, off);
    if (!lane) g_scores[b * 512 + (gw - b * NN)] = s;
}

// ---------------- feat2 : windowed softmax [i, min(i+3,510)] ----------------
__global__ void feat2_k(const float* __restrict__ feat) {
    int i = blockIdx.x, b = blockIdx.y;
    int end = min(i + 3, NN - 1), cnt = end - i + 1;
    float sc[4];
    float mx = -1e30f;
    for (int k = 0; k < cnt; k++) { sc[k] = g_scores[b * 512 + i + k]; mx = fmaxf(mx, sc[k]); }
    float sum = 0.f;
    for (int k = 0; k < cnt; k++) { sc[k] = expf(sc[k] - mx); sum += sc[k]; }
    float inv = 1.f / sum;
    size_t base = ((size_t)b * NN + i) * F_;
    for (int f = threadIdx.x; f < F_; f += blockDim.x) {
        float a = 0.f;
        for (int k = 0; k < cnt; k++) a += sc[k] * feat[base + (size_t)k * F_ + f];
        g_feat2[base + f] = a * inv;
    }
}

// ---------------- 128x128x8 SGEMM, 8x8 per-thread tile, double-buffered ----------------
// MODE 0: fe_iou = feat2 @ W_fe_iou^T + bias
// MODE 1: ff     = feat2[parents] @ W_fe_f^T + bias
// MODE 2: fc     = sigmoid(h[child] @ W_f^T + ff[parent]) * c[child]
// MODE 3: iou    = (h[c0]+h[c1]) @ W_iou^T + fe_iou[parent]
template <int MODE>
__global__ void __launch_bounds__(256, 2)
gemm_k(const float* __restrict__ W, const float* __restrict__ bias,
       int M, int N, int s, int np) {
    __shared__ __align__(16) float As[2][8][132];
    __shared__ __align__(16) float Ws[2][8][132];
    const int t = threadIdx.x;
    const int bm = blockIdx.y * 128, bn = blockIdx.x * 128;
    const int lr = t >> 1;            // 0..127 load row
    const int lk = (t & 1) * 4;       // 0 or 4
    const int tx = t & 15, ty = t >> 4;

    int row = bm + lr;
    bool aok = row < M;
    const float* ap = g_feat2;
    const float* ap2 = nullptr;
    if (aok) {
        if (MODE == 0) {
            ap = g_feat2 + (size_t)row * F_;
        } else if (MODE == 1) {
            int b = row / 255, p = row - b * 255;
            ap = g_feat2 + ((size_t)b * NN + p) * F_;
        } else if (MODE == 2) {
            int two = 2 * np;
            int b = row / two, cl = row - b * two;
            ap = g_h + ((size_t)b * NN + 2 * s + 1 + cl) * F_;
        } else {
            int b = row / np, pl = row - b * np;
            int p = s + pl;
            ap = g_h + ((size_t)b * NN + 2 * p + 1) * F_;
            ap2 = ap + F_;
        }
    }
    const float* wp = W + (size_t)(bn + lr) * F_;

    float acc[8][8] = {};

    // prologue: chunk 0 into buffer 0
    {
        float4 av = make_float4(0.f, 0.f, 0.f, 0.f);
        if (aok) {
            av = *(const float4*)(ap + lk);
            if (MODE == 3) {
                float4 a2 = *(const float4*)(ap2 + lk);
                av.x += a2.x; av.y += a2.y; av.z += a2.z; av.w += a2.w;
            }
        }
        float4 wv = *(const float4*)(wp + lk);
        As[0][lk + 0][lr] = av.x; As[0][lk + 1][lr] = av.y;
        As[0][lk + 2][lr] = av.z; As[0][lk + 3][lr] = av.w;
        Ws[0][lk + 0][lr] = wv.x; Ws[0][lk + 1][lr] = wv.y;
        Ws[0][lk + 2][lr] = wv.z; Ws[0][lk + 3][lr] = wv.w;
    }
    __syncthreads();

    int buf = 0;
    for (int k0 = 8; k0 <= 512; k0 += 8) {
        const bool more = (k0 < 512);
        float4 nav = make_float4(0.f, 0.f, 0.f, 0.f);
        float4 nwv = make_float4(0.f, 0.f, 0.f, 0.f);
        if (more) {
            if (aok) {
                nav = *(const float4*)(ap + k0 + lk);
                if (MODE == 3) {
                    float4 a2 = *(const float4*)(ap2 + k0 + lk);
                    nav.x += a2.x; nav.y += a2.y; nav.z += a2.z; nav.w += a2.w;
                }
            }
            nwv = *(const float4*)(wp + k0 + lk);
        }

        #pragma unroll
        for (int kk = 0; kk < 8; kk++) {
            float a[8], w[8];
            *(float4*)(a)     = *(const float4*)&As[buf][kk][ty * 8];
            *(float4*)(a + 4) = *(const float4*)&As[buf][kk][ty * 8 + 4];
            *(float4*)(w)     = *(const float4*)&Ws[buf][kk][tx * 8];
            *(float4*)(w + 4) = *(const float4*)&Ws[buf][kk][tx * 8 + 4];
            #pragma unroll
            for (int i2 = 0; i2 < 8; i2++)
                #pragma unroll
                for (int j = 0; j < 8; j++)
                    acc[i2][j] += a[i2] * w[j];
        }

        if (more) {
            int nb = buf ^ 1;
            As[nb][lk + 0][lr] = nav.x; As[nb][lk + 1][lr] = nav.y;
            As[nb][lk + 2][lr] = nav.z; As[nb][lk + 3][lr] = nav.w;
            Ws[nb][lk + 0][lr] = nwv.x; Ws[nb][lk + 1][lr] = nwv.y;
            Ws[nb][lk + 2][lr] = nwv.z; Ws[nb][lk + 3][lr] = nwv.w;
            __syncthreads();
            buf = nb;
        }
    }

    // epilogue
    #pragma unroll
    for (int i2 = 0; i2 < 8; i2++) {
        int m = bm + ty * 8 + i2;
        if (m >= M) continue;
        int b = 0, node = 0, p = 0;
        if (MODE == 2) {
            int two = 2 * np;
            b = m / two;
            int cl = m - b * two;
            node = 2 * s + 1 + cl;
            p = s + (cl >> 1);
        } else if (MODE == 3) {
            b = m / np;
            p = s + (m - b * np);
        }
        #pragma unroll
        for (int j4 = 0; j4 < 8; j4 += 4) {
            int n = bn + tx * 8 + j4;
            float4 v = make_float4(acc[i2][j4], acc[i2][j4 + 1], acc[i2][j4 + 2], acc[i2][j4 + 3]);
            if (MODE == 0) {
                float4 bi = *(const float4*)(bias + n);
                v.x += bi.x; v.y += bi.y; v.z += bi.z; v.w += bi.w;
                *(float4*)(g_fe_iou + (size_t)m * F3 + n) = v;
            } else if (MODE == 1) {
                float4 bi = *(const float4*)(bias + n);
                v.x += bi.x; v.y += bi.y; v.z += bi.z; v.w += bi.w;
                *(float4*)(g_ff + (size_t)m * F_ + n) = v;
            } else if (MODE == 2) {
                float4 ffv = *(const float4*)(g_ff + ((size_t)b * 255 + p) * F_ + n);
                float4 cv  = *(const float4*)(g_c + ((size_t)b * NN + node) * F_ + n);
                float4 o;
                o.x = sigf(v.x + ffv.x) * cv.x;
                o.y = sigf(v.y + ffv.y) * cv.y;
                o.z = sigf(v.z + ffv.z) * cv.z;
                o.w = sigf(v.w + ffv.w) * cv.w;
                *(float4*)(g_fc + (size_t)m * F_ + n) = o;
            } else {
                float4 fe = *(const float4*)(g_fe_iou + ((size_t)b * NN + p) * F3 + n);
                v.x += fe.x; v.y += fe.y; v.z += fe.z; v.w += fe.w;
                *(float4*)(g_iou + (size_t)m * F3 + n) = v;
            }
        }
    }
}

// ---------------- gates ----------------
__global__ void leafgate_k() {
    int idx = blockIdx.x * blockDim.x + threadIdx.x;
    int f = idx & 511;
    int r = idx >> 9;
    int b = r >> 8, l = r & 255;
    int node = 255 + l;
    size_t io = ((size_t)b * NN + node) * F3;
    float ig = g_fe_iou[io + f];
    float og = g_fe_iou[io + 512 + f];
    float ug = g_fe_iou[io + 1024 + f];
    float cn = sigf(ig) * fmaxf(ug, 0.f);
    float hn = sigf(og) * tanhf(cn);
    size_t ho = ((size_t)b * NN + node) * F_ + f;
    g_c[ho] = cn;
    g_h[ho] = hn;
}

__global__ void gate_k(int s, int np, int total) {
    int idx = blockIdx.x * blockDim.x + threadIdx.x;
    if (idx >= total) return;
    int f = idx & 511;
    int r = idx >> 9;
    int b = r / np, pl = r - b * np;
    int node = s + pl;
    size_t io = (size_t)r * F3;
    float ig = g_iou[io + f];
    float og = g_iou[io + 512 + f];
    float ug = g_iou[io + 1024 + f];
    float csum = g_fc[(size_t)(2 * r) * F_ + f] + g_fc[(size_t)(2 * r + 1) * F_ + f];
    float cn = sigf(ig) * fmaxf(ug, 0.f) + csum;
    float hn = sigf(og) * tanhf(cn);
    size_t ho = ((size_t)b * NN + node) * F_ + f;
    g_c[ho] = cn;
    g_h[ho] = hn;
}

// ---------------- final attention readout ----------------
__global__ void rscore_k() {
    int gw = (blockIdx.x * blockDim.x + threadIdx.x) >> 5;
    int lane = threadIdx.x & 31;
    if (gw >= B_ * NN) return;
    int b = gw / NN;
    const float4* hp = (const float4*)(g_h + (size_t)gw * F_);
    const float4* ep = (const float4*)(g_eforw + b * F_);
    float s = 0.f;
    for (int t = lane; t < 128; t += 32) {
        float4 h = hp[t], e = ep[t];
        s += h.x * e.x + h.y * e.y + h.z * e.z + h.w * e.w;
    }
    #pragma unroll
    for (int off = 16; off; off >>= 1) s += __shfl_xor_sync(0xffffffffu, s, off);
    if (!lane) g_r[b * 512 + (gw - b * NN)] = s;
}

__global__ void final_k(float* __restrict__ out) {
    __shared__ float red[128];
    __shared__ float pr[NN];
    int b = blockIdx.y, tid = threadIdx.x;
    float mx = -1e30f;
    for (int i = tid; i < NN; i += 128) mx = fmaxf(mx, g_r[b * 512 + i]);
    red[tid] = mx;
    __syncthreads();
    for (int o = 64; o; o >>= 1) {
        if (tid < o) red[tid] = fmaxf(red[tid], red[tid + o]);
        __syncthreads();
    }
    mx = red[0];
    __syncthreads();
    float sm = 0.f;
    for (int i = tid; i < NN; i += 128) {
        float e = expf(g_r[b * 512 + i] - mx);
        pr[i] = e;
        sm += e;
    }
    red[tid] = sm;
    __syncthreads();
    for (int o = 64; o; o >>= 1) {
        if (tid < o) red[tid] += red[tid + o];
        __syncthreads();
    }
    float inv = 1.f / red[0];
    __syncthreads();
    int f = blockIdx.x * 128 + tid;
    float acc = 0.f;
    for (int i = 0; i < NN; i++) acc += pr[i] * g_h[((size_t)b * NN + i) * F_ + f];
    out[b * F_ + f] = acc * inv;
}

// ---------------- launcher ----------------
extern "C" void kernel_launch(void* const* d_in, const int* in_sizes, int n_in,
                              void* d_out, int out_size) {
    const float* feat     = (const float*)d_in[0];
    const float* eh       = (const float*)d_in[5];
    const float* Wn       = (const float*)d_in[6];
    const float* Wf       = (const float*)d_in[7];
    const float* W_iou    = (const float*)d_in[8];
    const float* W_fe_iou = (const float*)d_in[9];
    const float* b_fe_iou = (const float*)d_in[10];
    const float* W_f      = (const float*)d_in[11];
    const float* W_fe_f   = (const float*)d_in[12];
    const float* b_fe_f   = (const float*)d_in[13];
    float* out = (float*)d_out;

    enode_k<<<dim3(64, 32, 2), 256>>>(eh, Wn, Wf);
    scores_k<<<2044, 256>>>(feat);
    feat2_k<<<dim3(NN, B_), 256>>>(feat);

    // fe_iou: M = 32*511 = 16352, N = 1536
    gemm_k<0><<<dim3(F3 / 128, (16352 + 127) / 128), 256>>>(W_fe_iou, b_fe_iou, 16352, F3, 0, 0);
    // ff: M = 32*255 = 8160, N = 512
    gemm_k<1><<<dim3(F_ / 128, (8160 + 127) / 128), 256>>>(W_fe_f, b_fe_f, 8160, F_, 0, 0);

    // level 0: leaves (nodes 255..510)
    leafgate_k<<<(B_ * 256 * F_) / 256, 256>>>();

    // levels 1..8 (bottom-up)
    for (int n = 1; n <= 8; n++) {
        int np = 1 << (8 - n);
        int s = np - 1;
        int Mf = B_ * 2 * np;
        int Mi = B_ * np;
        gemm_k<2><<<dim3(F_ / 128, (Mf + 127) / 128), 256>>>(W_f, nullptr, Mf, F_, s, np);
        gemm_k<3><<<dim3(F3 / 128, (Mi + 127) / 128), 256>>>(W_iou, nullptr, Mi, F3, s, np);
        int total = Mi * F_;
        gate_k<<<(total + 255) / 256, 256>>>(s, np, total);
    }

    rscore_k<<<2044, 256>>>();
    final_k<<<dim3(4, B_), 128>>>(out);
}

// round 4
// speedup vs baseline: 3.3809x; 3.3809x over previous
#include <cuda_runtime.h>
#include <cuda_bf16.h>
#include <math.h>
#include <cstdint>

#define B_ 32
#define NN 511
#define F_ 512
#define F3 1536

// ======================= scratch (static device globals) =======================
static __device__ __align__(16) float g_enode[B_ * F_];
static __device__ __align__(16) float g_eforw[B_ * F_];
static __device__ __align__(16) float g_scores[B_ * 512];
static __device__ __align__(16) float g_fe_iou[(size_t)B_ * NN * F3];
static __device__ __align__(16) float g_ff[(size_t)B_ * 255 * F_];
static __device__ __align__(16) float g_h[(size_t)B_ * NN * F_];
static __device__ __align__(16) float g_c[(size_t)B_ * NN * F_];
static __device__ __align__(16) float g_fc[(size_t)B_ * 256 * F_];
static __device__ __align__(16) float g_iou[(size_t)B_ * 128 * F3];
static __device__ __align__(16) float g_r[B_ * 512];
// bf16 hi/lo activation pairs
static __device__ __align__(16) __nv_bfloat16 g_f2h[(size_t)B_ * NN * F_];
static __device__ __align__(16) __nv_bfloat16 g_f2l[(size_t)B_ * NN * F_];
static __device__ __align__(16) __nv_bfloat16 g_hh[(size_t)B_ * NN * F_];
static __device__ __align__(16) __nv_bfloat16 g_hl[(size_t)B_ * NN * F_];
static __device__ __align__(16) __nv_bfloat16 g_hsh[(size_t)B_ * 128 * F_];
static __device__ __align__(16) __nv_bfloat16 g_hsl[(size_t)B_ * 128 * F_];
// bf16 hi/lo weights
static __device__ __align__(16) __nv_bfloat16 g_wfeiou_h[F3 * F_], g_wfeiou_l[F3 * F_];
static __device__ __align__(16) __nv_bfloat16 g_wfef_h[F_ * F_],  g_wfef_l[F_ * F_];
static __device__ __align__(16) __nv_bfloat16 g_wf_h[F_ * F_],    g_wf_l[F_ * F_];
static __device__ __align__(16) __nv_bfloat16 g_wiou_h[F3 * F_],  g_wiou_l[F3 * F_];

__device__ __forceinline__ float sigf(float x) { return 1.f / (1.f + expf(-x)); }
__device__ __forceinline__ void split_bf(float x, __nv_bfloat16& h, __nv_bfloat16& l) {
    h = __float2bfloat16(x);
    l = __float2bfloat16(x - __bfloat162float(h));
}

__device__ __forceinline__ uint32_t smem_u32(const void* p) {
    uint32_t a;
    asm("{ .reg .u64 t; cvta.to.shared.u64 t, %1; cvt.u32.u64 %0, t; }" : "=r"(a) : "l"(p));
    return a;
}

#define CP16(dst, src) \
    asm volatile("cp.async.cg.shared.global [%0], [%1], 16;" :: "r"(dst), "l"(src) : "memory")
#define CP_COMMIT() asm volatile("cp.async.commit_group;" ::: "memory")
template <int N>
__device__ __forceinline__ void cp_wait() {
    asm volatile("cp.async.wait_group %0;" :: "n"(N) : "memory");
}

__device__ __forceinline__ void mma16816(float* c, const uint32_t* a, const uint32_t* b) {
    asm volatile(
        "mma.sync.aligned.m16n8k16.row.col.f32.bf16.bf16.f32 "
        "{%0,%1,%2,%3}, {%4,%5,%6,%7}, {%8,%9}, {%0,%1,%2,%3};"
        : "+f"(c[0]), "+f"(c[1]), "+f"(c[2]), "+f"(c[3])
        : "r"(a[0]), "r"(a[1]), "r"(a[2]), "r"(a[3]), "r"(b[0]), "r"(b[1]));
}

__device__ __forceinline__ uint32_t lds32(const __nv_bfloat16* p) {
    return *(const uint32_t*)p;
}

// ======================= small kernels =======================
__global__ void conv_k(const float* __restrict__ src, __nv_bfloat16* __restrict__ dh,
                       __nv_bfloat16* __restrict__ dl, int n) {
    int i = blockIdx.x * 256 + threadIdx.x;
    if (i < n) split_bf(src[i], dh[i], dl[i]);
}

__global__ void enode_k(const float* __restrict__ eh, const float* __restrict__ Wn,
                        const float* __restrict__ Wf) {
    int warp = threadIdx.x >> 5, lane = threadIdx.x & 31;
    int j = blockIdx.x * 8 + warp, b = blockIdx.y;
    const float* W = blockIdx.z ? Wf : Wn;
    float* o = blockIdx.z ? g_eforw : g_enode;
    const float4* wr = (const float4*)(W + (size_t)j * 1024);
    const float4* er = (const float4*)(eh + (size_t)b * 1024);
    float s = 0.f;
    for (int t = lane; t < 256; t += 32) {
        float4 w = wr[t], e = er[t];
        s += w.x * e.x + w.y * e.y + w.z * e.z + w.w * e.w;
    }
    #pragma unroll
    for (int off = 16; off; off >>= 1) s += __shfl_xor_sync(0xffffffffu, s, off);
    if (!lane) o[b * F_ + j] = s;
}

__global__ void scores_k(const float* __restrict__ feat) {
    int gw = (blockIdx.x * blockDim.x + threadIdx.x) >> 5;
    int lane = threadIdx.x & 31;
    if (gw >= B_ * NN) return;
    int b = gw / NN;
    const float4* fr = (const float4*)(feat + (size_t)gw * F_);
    const float4* er = (const float4*)(g_enode + b * F_);
    float s = 0.f;
    for (int t = lane; t < 128; t += 32) {
        float4 f = fr[t], e = er[t];
        s += f.x * e.x + f.y * e.y + f.z * e.z + f.w * e.w;
    }
    #pragma unroll
    for (int off = 16; off; off >>= 1) s += __shfl_xor_sync(0xffffffffu, s, off);
    if (!lane) g_scores[b * 512 + (gw - b * NN)] = s;
}

__global__ void feat2_k(const float* __restrict__ feat) {
    int i = blockIdx.x, b = blockIdx.y;
    int end = min(i + 3, NN - 1), cnt = end - i + 1;
    float sc[4];
    float mx = -1e30f;
    for (int k = 0; k < cnt; k++) { sc[k] = g_scores[b * 512 + i + k]; mx = fmaxf(mx, sc[k]); }
    float sum = 0.f;
    for (int k = 0; k < cnt; k++) { sc[k] = expf(sc[k] - mx); sum += sc[k]; }
    float inv = 1.f / sum;
    size_t base = ((size_t)b * NN + i) * F_;
    for (int f = threadIdx.x; f < F_; f += blockDim.x) {
        float a = 0.f;
        for (int k = 0; k < cnt; k++) a += sc[k] * feat[base + (size_t)k * F_ + f];
        a *= inv;
        split_bf(a, g_f2h[base + f], g_f2l[base + f]);
    }
}

// ======================= HMMA GEMM (bf16 hi/lo 3-pass, fp32 acc) =======================
// C = A @ W^T, K=512. Block tile 128x128x32, 8 warps (2M x 4N), warp tile 64x32.
// MODE 0: fe_iou = feat2 @ W_fe_iou^T + bias
// MODE 1: ff     = feat2[parents] @ W_fe_f^T + bias
// MODE 2: fc     = sigmoid(h[child] @ W_f^T + ff[parent]) * c[child]
// MODE 3: iou    = hsum @ W_iou^T + fe_iou[parent]
// smem per stage: Ah,Al,Wh,Wl each 128 rows x 40 bf16 (80B padded) = 10240B; 2 stages.
#define TILE_B 10240
#define STAGE_B (4 * TILE_B)
#define SMEM_TOT (2 * STAGE_B)

template <int MODE>
__global__ void __launch_bounds__(256)
gemm_hmma(const float* __restrict__ bias, int M, int s, int np) {
    extern __shared__ char smem[];
    const uint32_t sb = smem_u32(smem);
    const int tid = threadIdx.x;
    const int warp = tid >> 5, lane = tid & 31;
    const int wm = warp >> 2, wn = warp & 3;
    const int qrow = lane >> 2, qcol = (lane & 3) * 2;
    const int bm = blockIdx.y * 128, bn = blockIdx.x * 128;

    const __nv_bfloat16 *Ah, *Al, *Wh, *Wl;
    if (MODE == 0) { Ah = g_f2h; Al = g_f2l; Wh = g_wfeiou_h; Wl = g_wfeiou_l; }
    else if (MODE == 1) { Ah = g_f2h; Al = g_f2l; Wh = g_wfef_h; Wl = g_wfef_l; }
    else if (MODE == 2) { Ah = g_hh; Al = g_hl; Wh = g_wf_h; Wl = g_wf_l; }
    else { Ah = g_hsh; Al = g_hsl; Wh = g_wiou_h; Wl = g_wiou_l; }

    // --- load geometry: each thread covers 2 rows (row0, row0+64), one 16B quad ---
    const int quad = tid & 3;
    const int row0 = tid >> 2;
    int ar0, ar1;
    {
        int rA = min(bm + row0, M - 1);
        int rB = min(bm + row0 + 64, M - 1);
        if (MODE == 0 || MODE == 3) { ar0 = rA; ar1 = rB; }
        else if (MODE == 1) {
            int b0 = rA / 255; ar0 = b0 * NN + (rA - b0 * 255);
            int b1 = rB / 255; ar1 = b1 * NN + (rB - b1 * 255);
        } else {
            int two = 2 * np;
            int b0 = rA / two; ar0 = b0 * NN + 2 * s + 1 + (rA - b0 * two);
            int b1 = rB / two; ar1 = b1 * NN + 2 * s + 1 + (rB - b1 * two);
        }
    }
    const int a00 = ar0 * F_ + quad * 8;
    const int a01 = ar1 * F_ + quad * 8;
    const int w00 = (bn + row0) * F_ + quad * 8;
    const int w01 = (bn + row0 + 64) * F_ + quad * 8;
    const uint32_t d0 = (uint32_t)(row0 * 80 + quad * 16);
    const uint32_t d1 = d0 + 64 * 80;

#define LOAD_CHUNK(cidx, stg) do {                                         \
    int k0 = (cidx) * 32;                                                  \
    uint32_t s0 = sb + (stg) * STAGE_B;                                    \
    CP16(s0 + d0,              Ah + a00 + k0);                             \
    CP16(s0 + d1,              Ah + a01 + k0);                             \
    CP16(s0 + TILE_B + d0,     Al + a00 + k0);                             \
    CP16(s0 + TILE_B + d1,     Al + a01 + k0);                             \
    CP16(s0 + 2 * TILE_B + d0, Wh + w00 + k0);                             \
    CP16(s0 + 2 * TILE_B + d1, Wh + w01 + k0);                             \
    CP16(s0 + 3 * TILE_B + d0, Wl + w00 + k0);                             \
    CP16(s0 + 3 * TILE_B + d1, Wl + w01 + k0);                             \
    CP_COMMIT();                                                          \
} while (0)

    float acc[4][4][4] = {};

    LOAD_CHUNK(0, 0);

    for (int c = 0; c < 16; c++) {
        if (c < 15) {
            LOAD_CHUNK(c + 1, (c + 1) & 1);
            cp_wait<1>();
        } else {
            cp_wait<0>();
        }
        __syncthreads();

        const __nv_bfloat16* sA_h = (const __nv_bfloat16*)(smem + (c & 1) * STAGE_B);
        const __nv_bfloat16* sA_l = sA_h + 5120;
        const __nv_bfloat16* sW_h = sA_h + 10240;
        const __nv_bfloat16* sW_l = sA_h + 15360;

        #pragma unroll
        for (int kk = 0; kk < 2; kk++) {
            uint32_t ah[4][4], al[4][4], bh[4][2], bl[4][2];
            #pragma unroll
            for (int mf = 0; mf < 4; mf++) {
                int off = (wm * 64 + mf * 16 + qrow) * 40 + kk * 16 + qcol;
                ah[mf][0] = lds32(sA_h + off);
                ah[mf][1] = lds32(sA_h + off + 320);
                ah[mf][2] = lds32(sA_h + off + 8);
                ah[mf][3] = lds32(sA_h + off + 328);
                al[mf][0] = lds32(sA_l + off);
                al[mf][1] = lds32(sA_l + off + 320);
                al[mf][2] = lds32(sA_l + off + 8);
                al[mf][3] = lds32(sA_l + off + 328);
            }
            #pragma unroll
            for (int nf = 0; nf < 4; nf++) {
                int off = (wn * 32 + nf * 8 + qrow) * 40 + kk * 16 + qcol;
                bh[nf][0] = lds32(sW_h + off);
                bh[nf][1] = lds32(sW_h + off + 8);
                bl[nf][0] = lds32(sW_l + off);
                bl[nf][1] = lds32(sW_l + off + 8);
            }
            #pragma unroll
            for (int mf = 0; mf < 4; mf++)
                #pragma unroll
                for (int nf = 0; nf < 4; nf++) {
                    mma16816(acc[mf][nf], ah[mf], bh[nf]);
                    mma16816(acc[mf][nf], ah[mf], bl[nf]);
                    mma16816(acc[mf][nf], al[mf], bh[nf]);
                }
        }
        __syncthreads();
    }

    // --- epilogue ---
    #pragma unroll
    for (int mf = 0; mf < 4; mf++) {
        #pragma unroll
        for (int half = 0; half < 2; half++) {
            int m = bm + wm * 64 + mf * 16 + qrow + half * 8;
            if (m >= M) continue;
            int b = 0, node = 0, p = 0;
            if (MODE == 2) {
                int two = 2 * np;
                b = m / two;
                int cl = m - b * two;
                node = 2 * s + 1 + cl;
                p = s + (cl >> 1);
            } else if (MODE == 3) {
                b = m / np;
                p = s + (m - b * np);
            }
            #pragma unroll
            for (int nf = 0; nf < 4; nf++) {
                int n = bn + wn * 32 + nf * 8 + qcol;
                float2 v = make_float2(acc[mf][nf][half * 2], acc[mf][nf][half * 2 + 1]);
                if (MODE == 0) {
                    float2 bi = *(const float2*)(bias + n);
                    v.x += bi.x; v.y += bi.y;
                    *(float2*)(g_fe_iou + (size_t)m * F3 + n) = v;
                } else if (MODE == 1) {
                    float2 bi = *(const float2*)(bias + n);
                    v.x += bi.x; v.y += bi.y;
                    *(float2*)(g_ff + (size_t)m * F_ + n) = v;
                } else if (MODE == 2) {
                    float2 ffv = *(const float2*)(g_ff + ((size_t)b * 255 + p) * F_ + n);
                    float2 cv  = *(const float2*)(g_c + ((size_t)b * NN + node) * F_ + n);
                    float2 o;
                    o.x = sigf(v.x + ffv.x) * cv.x;
                    o.y = sigf(v.y + ffv.y) * cv.y;
                    *(float2*)(g_fc + (size_t)m * F_ + n) = o;
                } else {
                    float2 fe = *(const float2*)(g_fe_iou + ((size_t)b * NN + p) * F3 + n);
                    v.x += fe.x; v.y += fe.y;
                    *(float2*)(g_iou + (size_t)m * F3 + n) = v;
                }
            }
        }
    }
}

// ======================= gates / hsum =======================
__global__ void leafgate_k() {
    int idx = blockIdx.x * blockDim.x + threadIdx.x;
    int f = idx & 511, r = idx >> 9;
    int b = r >> 8, l = r & 255;
    int node = 255 + l;
    size_t io = ((size_t)b * NN + node) * F3;
    float cn = sigf(g_fe_iou[io + f]) * fmaxf(g_fe_iou[io + 1024 + f], 0.f);
    float hn = sigf(g_fe_iou[io + 512 + f]) * tanhf(cn);
    size_t ho = ((size_t)b * NN + node) * F_ + f;
    g_c[ho] = cn;
    g_h[ho] = hn;
    split_bf(hn, g_hh[ho], g_hl[ho]);
}

__global__ void gate_k(int s, int np, int total) {
    int idx = blockIdx.x * blockDim.x + threadIdx.x;
    if (idx >= total) return;
    int f = idx & 511, r = idx >> 9;
    int b = r / np, pl = r - b * np;
    int node = s + pl;
    size_t io = (size_t)r * F3;
    float csum = g_fc[(size_t)(2 * r) * F_ + f] + g_fc[(size_t)(2 * r + 1) * F_ + f];
    float cn = sigf(g_iou[io + f]) * fmaxf(g_iou[io + 1024 + f], 0.f) + csum;
    float hn = sigf(g_iou[io + 512 + f]) * tanhf(cn);
    size_t ho = ((size_t)b * NN + node) * F_ + f;
    g_c[ho] = cn;
    g_h[ho] = hn;
    split_bf(hn, g_hh[ho], g_hl[ho]);
}

__global__ void hsum_k(int s, int np, int total) {
    int idx = blockIdx.x * blockDim.x + threadIdx.x;
    if (idx >= total) return;
    int f = idx & 511, r = idx >> 9;
    int b = r / np, pl = r - b * np;
    int pp = s + pl;
    float v = g_h[((size_t)b * NN + 2 * pp + 1) * F_ + f] + g_h[((size_t)b * NN + 2 * pp + 2) * F_ + f];
    split_bf(v, g_hsh[(size_t)r * F_ + f], g_hsl[(size_t)r * F_ + f]);
}

// ======================= readout =======================
__global__ void rscore_k() {
    int gw = (blockIdx.x * blockDim.x + threadIdx.x) >> 5;
    int lane = threadIdx.x & 31;
    if (gw >= B_ * NN) return;
    int b = gw / NN;
    const float4* hp = (const float4*)(g_h + (size_t)gw * F_);
    const float4* ep = (const float4*)(g_eforw + b * F_);
    float s = 0.f;
    for (int t = lane; t < 128; t += 32) {
        float4 h = hp[t], e = ep[t];
        s += h.x * e.x + h.y * e.y + h.z * e.z + h.w * e.w;
    }
    #pragma unroll
    for (int off = 16; off; off >>= 1) s += __shfl_xor_sync(0xffffffffu, s, off);
    if (!lane) g_r[b * 512 + (gw - b * NN)] = s;
}

__global__ void final_k(float* __restrict__ out) {
    __shared__ float red[128];
    __shared__ float pr[NN];
    int b = blockIdx.y, tid = threadIdx.x;
    float mx = -1e30f;
    for (int i = tid; i < NN; i += 128) mx = fmaxf(mx, g_r[b * 512 + i]);
    red[tid] = mx;
    __syncthreads();
    for (int o = 64; o; o >>= 1) {
        if (tid < o) red[tid] = fmaxf(red[tid], red[tid + o]);
        __syncthreads();
    }
    mx = red[0];
    __syncthreads();
    float sm = 0.f;
    for (int i = tid; i < NN; i += 128) {
        float e = expf(g_r[b * 512 + i] - mx);
        pr[i] = e;
        sm += e;
    }
    red[tid] = sm;
    __syncthreads();
    for (int o = 64; o; o >>= 1) {
        if (tid < o) red[tid] += red[tid + o];
        __syncthreads();
    }
    float inv = 1.f / red[0];
    __syncthreads();
    int f = blockIdx.x * 128 + tid;
    float acc = 0.f;
    for (int i = 0; i < NN; i++) acc += pr[i] * g_h[((size_t)b * NN + i) * F_ + f];
    out[b * F_ + f] = acc * inv;
}

// ======================= launcher =======================
extern "C" void kernel_launch(void* const* d_in, const int* in_sizes, int n_in,
                              void* d_out, int out_size) {
    const float* feat     = (const float*)d_in[0];
    const float* eh       = (const float*)d_in[5];
    const float* Wn       = (const float*)d_in[6];
    const float* Wf       = (const float*)d_in[7];
    const float* W_iou    = (const float*)d_in[8];
    const float* W_fe_iou = (const float*)d_in[9];
    const float* b_fe_iou = (const float*)d_in[10];
    const float* W_f      = (const float*)d_in[11];
    const float* W_fe_f   = (const float*)d_in[12];
    const float* b_fe_f   = (const float*)d_in[13];
    float* out = (float*)d_out;

    static bool attr_done = false;
    if (!attr_done) {
        cudaFuncSetAttribute(gemm_hmma<0>, cudaFuncAttributeMaxDynamicSharedMemorySize, SMEM_TOT);
        cudaFuncSetAttribute(gemm_hmma<1>, cudaFuncAttributeMaxDynamicSharedMemorySize, SMEM_TOT);
        cudaFuncSetAttribute(gemm_hmma<2>, cudaFuncAttributeMaxDynamicSharedMemorySize, SMEM_TOT);
        cudaFuncSetAttribute(gemm_hmma<3>, cudaFuncAttributeMaxDynamicSharedMemorySize, SMEM_TOT);
        attr_done = true;
    }

    // weight conversion fp32 -> bf16 hi/lo
    __nv_bfloat16 *wh, *wl;
    cudaGetSymbolAddress((void**)&wh, g_wfeiou_h); cudaGetSymbolAddress((void**)&wl, g_wfeiou_l);
    conv_k<<<(F3 * F_ + 255) / 256, 256>>>(W_fe_iou, wh, wl, F3 * F_);
    cudaGetSymbolAddress((void**)&wh, g_wfef_h); cudaGetSymbolAddress((void**)&wl, g_wfef_l);
    conv_k<<<(F_ * F_ + 255) / 256, 256>>>(W_fe_f, wh, wl, F_ * F_);
    cudaGetSymbolAddress((void**)&wh, g_wf_h); cudaGetSymbolAddress((void**)&wl, g_wf_l);
    conv_k<<<(F_ * F_ + 255) / 256, 256>>>(W_f, wh, wl, F_ * F_);
    cudaGetSymbolAddress((void**)&wh, g_wiou_h); cudaGetSymbolAddress((void**)&wl, g_wiou_l);
    conv_k<<<(F3 * F_ + 255) / 256, 256>>>(W_iou, wh, wl, F3 * F_);

    enode_k<<<dim3(64, 32, 2), 256>>>(eh, Wn, Wf);
    scores_k<<<2044, 256>>>(feat);
    feat2_k<<<dim3(NN, B_), 256>>>(feat);

    // fe_iou: M = 16352, N = 1536
    gemm_hmma<0><<<dim3(12, 128), 256, SMEM_TOT>>>(b_fe_iou, 16352, 0, 0);
    // ff: M = 8160, N = 512
    gemm_hmma<1><<<dim3(4, 64), 256, SMEM_TOT>>>(b_fe_f, 8160, 0, 0);

    leafgate_k<<<(B_ * 256 * F_) / 256, 256>>>();

    for (int n = 1; n <= 8; n++) {
        int np = 1 << (8 - n);
        int s = np - 1;
        int Mf = B_ * 2 * np;
        int Mi = B_ * np;
        hsum_k<<<(Mi * F_ + 255) / 256, 256>>>(s, np, Mi * F_);
        gemm_hmma<2><<<dim3(4, (Mf + 127) / 128), 256, SMEM_TOT>>>(nullptr, Mf, s, np);
        gemm_hmma<3><<<dim3(12, (Mi + 127) / 128), 256, SMEM_TOT>>>(nullptr, Mi, s, np);
        gate_k<<<(Mi * F_ + 255) / 256, 256>>>(s, np, Mi * F_);
    }

    rscore_k<<<2044, 256>>>();
    final_k<<<dim3(4, B_), 128>>>(out);
}

// round 5
// speedup vs baseline: 3.8706x; 1.1449x over previous
#include <cuda_runtime.h>
#include <cuda_bf16.h>
#include <math.h>
#include <cstdint>

#define B_ 32
#define NN 511
#define F_ 512
#define F3 1536

// ======================= scratch (static device globals) =======================
static __device__ __align__(16) float g_enode[B_ * F_];
static __device__ __align__(16) float g_eforw[B_ * F_];
static __device__ __align__(16) float g_scores[B_ * 512];
static __device__ __align__(16) float g_fe_iou[(size_t)B_ * NN * F3];
static __device__ __align__(16) float g_ff[(size_t)B_ * 255 * F_];
static __device__ __align__(16) float g_h[(size_t)B_ * NN * F_];
static __device__ __align__(16) float g_c[(size_t)B_ * NN * F_];
static __device__ __align__(16) float g_fc[(size_t)B_ * 256 * F_];
static __device__ __align__(16) float g_iou[(size_t)B_ * 128 * F3];
static __device__ __align__(16) float g_r[B_ * 512];
// bf16 hi/lo activation pairs
static __device__ __align__(16) __nv_bfloat16 g_f2h[(size_t)B_ * NN * F_];
static __device__ __align__(16) __nv_bfloat16 g_f2l[(size_t)B_ * NN * F_];
static __device__ __align__(16) __nv_bfloat16 g_hh[(size_t)B_ * NN * F_];
static __device__ __align__(16) __nv_bfloat16 g_hl[(size_t)B_ * NN * F_];
static __device__ __align__(16) __nv_bfloat16 g_hsh[(size_t)B_ * 128 * F_];
static __device__ __align__(16) __nv_bfloat16 g_hsl[(size_t)B_ * 128 * F_];
// bf16 hi/lo weights
static __device__ __align__(16) __nv_bfloat16 g_wfeiou_h[F3 * F_], g_wfeiou_l[F3 * F_];
static __device__ __align__(16) __nv_bfloat16 g_wfef_h[F_ * F_],  g_wfef_l[F_ * F_];
static __device__ __align__(16) __nv_bfloat16 g_wf_h[F_ * F_],    g_wf_l[F_ * F_];
static __device__ __align__(16) __nv_bfloat16 g_wiou_h[F3 * F_],  g_wiou_l[F3 * F_];

__device__ __forceinline__ float sigf(float x) { return 1.f / (1.f + expf(-x)); }
__device__ __forceinline__ void split_bf(float x, __nv_bfloat16& h, __nv_bfloat16& l) {
    h = __float2bfloat16(x);
    l = __float2bfloat16(x - __bfloat162float(h));
}

__device__ __forceinline__ uint32_t smem_u32(const void* p) {
    uint32_t a;
    asm("{ .reg .u64 t; cvta.to.shared.u64 t, %1; cvt.u32.u64 %0, t; }" : "=r"(a) : "l"(p));
    return a;
}

#define CP16(dst, src) \
    asm volatile("cp.async.cg.shared.global [%0], [%1], 16;" :: "r"(dst), "l"(src) : "memory")
#define CP_COMMIT() asm volatile("cp.async.commit_group;" ::: "memory")
template <int N>
__device__ __forceinline__ void cp_wait() {
    asm volatile("cp.async.wait_group %0;" :: "n"(N) : "memory");
}

__device__ __forceinline__ void mma16816(float* c, const uint32_t* a, const uint32_t* b) {
    asm volatile(
        "mma.sync.aligned.m16n8k16.row.col.f32.bf16.bf16.f32 "
        "{%0,%1,%2,%3}, {%4,%5,%6,%7}, {%8,%9}, {%0,%1,%2,%3};"
        : "+f"(c[0]), "+f"(c[1]), "+f"(c[2]), "+f"(c[3])
        : "r"(a[0]), "r"(a[1]), "r"(a[2]), "r"(a[3]), "r"(b[0]), "r"(b[1]));
}

__device__ __forceinline__ void ldsm4(uint32_t& r0, uint32_t& r1, uint32_t& r2, uint32_t& r3,
                                      uint32_t addr) {
    asm volatile("ldmatrix.sync.aligned.m8n8.x4.shared.b16 {%0,%1,%2,%3}, [%4];"
                 : "=r"(r0), "=r"(r1), "=r"(r2), "=r"(r3) : "r"(addr));
}

// ======================= small kernels =======================
__global__ void conv_all(const float* __restrict__ s0, const float* __restrict__ s1,
                         const float* __restrict__ s2, const float* __restrict__ s3) {
    int i = blockIdx.x * 256 + threadIdx.x;  // total 2097152
    if (i < 786432) {
        split_bf(s0[i], g_wfeiou_h[i], g_wfeiou_l[i]);
    } else if (i < 1048576) {
        int j = i - 786432;
        split_bf(s1[j], g_wfef_h[j], g_wfef_l[j]);
    } else if (i < 1310720) {
        int j = i - 1048576;
        split_bf(s2[j], g_wf_h[j], g_wf_l[j]);
    } else {
        int j = i - 1310720;
        split_bf(s3[j], g_wiou_h[j], g_wiou_l[j]);
    }
}

__global__ void enode_k(const float* __restrict__ eh, const float* __restrict__ Wn,
                        const float* __restrict__ Wf) {
    int warp = threadIdx.x >> 5, lane = threadIdx.x & 31;
    int j = blockIdx.x * 8 + warp, b = blockIdx.y;
    const float* W = blockIdx.z ? Wf : Wn;
    float* o = blockIdx.z ? g_eforw : g_enode;
    const float4* wr = (const float4*)(W + (size_t)j * 1024);
    const float4* er = (const float4*)(eh + (size_t)b * 1024);
    float s = 0.f;
    for (int t = lane; t < 256; t += 32) {
        float4 w = wr[t], e = er[t];
        s += w.x * e.x + w.y * e.y + w.z * e.z + w.w * e.w;
    }
    #pragma unroll
    for (int off = 16; off; off >>= 1) s += __shfl_xor_sync(0xffffffffu, s, off);
    if (!lane) o[b * F_ + j] = s;
}

__global__ void scores_k(const float* __restrict__ feat) {
    int gw = (blockIdx.x * blockDim.x + threadIdx.x) >> 5;
    int lane = threadIdx.x & 31;
    if (gw >= B_ * NN) return;
    int b = gw / NN;
    const float4* fr = (const float4*)(feat + (size_t)gw * F_);
    const float4* er = (const float4*)(g_enode + b * F_);
    float s = 0.f;
    for (int t = lane; t < 128; t += 32) {
        float4 f = fr[t], e = er[t];
        s += f.x * e.x + f.y * e.y + f.z * e.z + f.w * e.w;
    }
    #pragma unroll
    for (int off = 16; off; off >>= 1) s += __shfl_xor_sync(0xffffffffu, s, off);
    if (!lane) g_scores[b * 512 + (gw - b * NN)] = s;
}

__global__ void feat2_k(const float* __restrict__ feat) {
    int i = blockIdx.x, b = blockIdx.y;
    int end = min(i + 3, NN - 1), cnt = end - i + 1;
    float sc[4];
    float mx = -1e30f;
    for (int k = 0; k < cnt; k++) { sc[k] = g_scores[b * 512 + i + k]; mx = fmaxf(mx, sc[k]); }
    float sum = 0.f;
    for (int k = 0; k < cnt; k++) { sc[k] = expf(sc[k] - mx); sum += sc[k]; }
    float inv = 1.f / sum;
    size_t base = ((size_t)b * NN + i) * F_;
    for (int f = threadIdx.x; f < F_; f += blockDim.x) {
        float a = 0.f;
        for (int k = 0; k < cnt; k++) a += sc[k] * feat[base + (size_t)k * F_ + f];
        a *= inv;
        split_bf(a, g_f2h[base + f], g_f2l[base + f]);
    }
}

// ======================= HMMA GEMM core (bf16 hi/lo 3-pass, fp32 acc) =======================
// Block tile 128x128x32, 8 warps (2M x 4N), warp tile 64x32, ldmatrix fragments.
// MODE 0: fe_iou = feat2 @ W_fe_iou^T + bias
// MODE 1: ff     = feat2[parents] @ W_fe_f^T + bias
// MODE 2: fc     = sigmoid(h[child] @ W_f^T + ff[parent]) * c[child]
// MODE 3: iou    = hsum @ W_iou^T + fe_iou[parent]
#define TILE_B 10240
#define STAGE_B (4 * TILE_B)
#define SMEM_TOT (2 * STAGE_B)

template <int MODE>
__device__ __forceinline__ void gemm_core(char* smem, int bm, int bn,
                                          const float* __restrict__ bias,
                                          int M, int s, int np) {
    const uint32_t sb = smem_u32(smem);
    const int tid = threadIdx.x;
    const int warp = tid >> 5, lane = tid & 31;
    const int wm = warp >> 2, wn = warp & 3;
    const int qrow = lane >> 2, qcol = (lane & 3) * 2;

    const __nv_bfloat16 *Ah, *Al, *Wh, *Wl;
    if (MODE == 0) { Ah = g_f2h; Al = g_f2l; Wh = g_wfeiou_h; Wl = g_wfeiou_l; }
    else if (MODE == 1) { Ah = g_f2h; Al = g_f2l; Wh = g_wfef_h; Wl = g_wfef_l; }
    else if (MODE == 2) { Ah = g_hh; Al = g_hl; Wh = g_wf_h; Wl = g_wf_l; }
    else { Ah = g_hsh; Al = g_hsl; Wh = g_wiou_h; Wl = g_wiou_l; }

    // --- cp.async geometry: each thread covers 2 rows (row0, row0+64), one 16B quad ---
    const int quad = tid & 3;
    const int row0 = tid >> 2;
    int ar0, ar1;
    {
        int rA = min(bm + row0, M - 1);
        int rB = min(bm + row0 + 64, M - 1);
        if (MODE == 0 || MODE == 3) { ar0 = rA; ar1 = rB; }
        else if (MODE == 1) {
            int b0 = rA / 255; ar0 = b0 * NN + (rA - b0 * 255);
            int b1 = rB / 255; ar1 = b1 * NN + (rB - b1 * 255);
        } else {
            int two = 2 * np;
            int b0 = rA / two; ar0 = b0 * NN + 2 * s + 1 + (rA - b0 * two);
            int b1 = rB / two; ar1 = b1 * NN + 2 * s + 1 + (rB - b1 * two);
        }
    }
    const int a00 = ar0 * F_ + quad * 8;
    const int a01 = ar1 * F_ + quad * 8;
    const int w00 = (bn + row0) * F_ + quad * 8;
    const int w01 = (bn + row0 + 64) * F_ + quad * 8;
    const uint32_t d0 = (uint32_t)(row0 * 80 + quad * 16);
    const uint32_t d1 = d0 + 64 * 80;

    // --- ldmatrix lane offsets ---
    const uint32_t a_l = (uint32_t)((wm * 64 + (lane & 15)) * 80 + (lane >> 4) * 16);
    const uint32_t b_l = (uint32_t)((wn * 32 + ((lane >> 4) & 1) * 8 + (lane & 7)) * 80 +
                                    ((lane >> 3) & 1) * 16);

#define LOAD_CHUNK(cidx, stgi) do {                                        \
    int k0 = (cidx) * 32;                                                  \
    uint32_t s0a = sb + (stgi) * STAGE_B;                                  \
    CP16(s0a + d0,              Ah + a00 + k0);                            \
    CP16(s0a + d1,              Ah + a01 + k0);                            \
    CP16(s0a + TILE_B + d0,     Al + a00 + k0);                            \
    CP16(s0a + TILE_B + d1,     Al + a01 + k0);                            \
    CP16(s0a + 2 * TILE_B + d0, Wh + w00 + k0);                            \
    CP16(s0a + 2 * TILE_B + d1, Wh + w01 + k0);                            \
    CP16(s0a + 3 * TILE_B + d0, Wl + w00 + k0);                            \
    CP16(s0a + 3 * TILE_B + d1, Wl + w01 + k0);                            \
    CP_COMMIT();                                                          \
} while (0)

    float acc[4][4][4] = {};

    LOAD_CHUNK(0, 0);

    for (int c = 0; c < 16; c++) {
        if (c < 15) {
            LOAD_CHUNK(c + 1, (c + 1) & 1);
            cp_wait<1>();
        } else {
            cp_wait<0>();
        }
        __syncthreads();

        const uint32_t stg = sb + (c & 1) * STAGE_B;
        #pragma unroll
        for (int kk = 0; kk < 2; kk++) {
            uint32_t ah[4][4], al[4][4], bh[2][4], bl[2][4];
            #pragma unroll
            for (int mf = 0; mf < 4; mf++) {
                uint32_t aaddr = stg + a_l + mf * 1280 + kk * 32;
                ldsm4(ah[mf][0], ah[mf][1], ah[mf][2], ah[mf][3], aaddr);
                ldsm4(al[mf][0], al[mf][1], al[mf][2], al[mf][3], aaddr + TILE_B);
            }
            #pragma unroll
            for (int p = 0; p < 2; p++) {
                uint32_t baddr = stg + 2 * TILE_B + b_l + p * 1280 + kk * 32;
                ldsm4(bh[p][0], bh[p][1], bh[p][2], bh[p][3], baddr);
                ldsm4(bl[p][0], bl[p][1], bl[p][2], bl[p][3], baddr + TILE_B);
            }
            #pragma unroll
            for (int mf = 0; mf < 4; mf++)
                #pragma unroll
                for (int p = 0; p < 2; p++)
                    #pragma unroll
                    for (int q = 0; q < 2; q++) {
                        int nf = p * 2 + q;
                        mma16816(acc[mf][nf], ah[mf], &bh[p][2 * q]);
                        mma16816(acc[mf][nf], ah[mf], &bl[p][2 * q]);
                        mma16816(acc[mf][nf], al[mf], &bh[p][2 * q]);
                    }
        }
        __syncthreads();
    }
#undef LOAD_CHUNK

    // --- epilogue ---
    #pragma unroll
    for (int mf = 0; mf < 4; mf++) {
        #pragma unroll
        for (int half = 0; half < 2; half++) {
            int m = bm + wm * 64 + mf * 16 + qrow + half * 8;
            if (m >= M) continue;
            int b = 0, node = 0, p = 0;
            if (MODE == 2) {
                int two = 2 * np;
                b = m / two;
                int cl = m - b * two;
                node = 2 * s + 1 + cl;
                p = s + (cl >> 1);
            } else if (MODE == 3) {
                b = m / np;
                p = s + (m - b * np);
            }
            #pragma unroll
            for (int nf = 0; nf < 4; nf++) {
                int n = bn + wn * 32 + nf * 8 + qcol;
                float2 v = make_float2(acc[mf][nf][half * 2], acc[mf][nf][half * 2 + 1]);
                if (MODE == 0) {
                    float2 bi = *(const float2*)(bias + n);
                    v.x += bi.x; v.y += bi.y;
                    *(float2*)(g_fe_iou + (size_t)m * F3 + n) = v;
                } else if (MODE == 1) {
                    float2 bi = *(const float2*)(bias + n);
                    v.x += bi.x; v.y += bi.y;
                    *(float2*)(g_ff + (size_t)m * F_ + n) = v;
                } else if (MODE == 2) {
                    float2 ffv = *(const float2*)(g_ff + ((size_t)b * 255 + p) * F_ + n);
                    float2 cv  = *(const float2*)(g_c + ((size_t)b * NN + node) * F_ + n);
                    float2 o;
                    o.x = sigf(v.x + ffv.x) * cv.x;
                    o.y = sigf(v.y + ffv.y) * cv.y;
                    *(float2*)(g_fc + (size_t)m * F_ + n) = o;
                } else {
                    float2 fe = *(const float2*)(g_fe_iou + ((size_t)b * NN + p) * F3 + n);
                    v.x += fe.x; v.y += fe.y;
                    *(float2*)(g_iou + (size_t)m * F3 + n) = v;
                }
            }
        }
    }
}

template <int MODE>
__global__ void __launch_bounds__(256)
gemm_hmma(const float* __restrict__ bias, int M) {
    extern __shared__ char smem[];
    gemm_core<MODE>(smem, blockIdx.y * 128, blockIdx.x * 128, bias, M, 0, 0);
}

// fused per-level kernel: fc blocks first, iou blocks after
__global__ void __launch_bounds__(256)
level_k(int s, int np, int yF, int Mf, int Mi) {
    extern __shared__ char smem[];
    int bx = blockIdx.x;
    if (bx < 4 * yF) {
        gemm_core<2>(smem, (bx >> 2) * 128, (bx & 3) * 128, nullptr, Mf, s, np);
    } else {
        bx -= 4 * yF;
        gemm_core<3>(smem, (bx / 12) * 128, (bx % 12) * 128, nullptr, Mi, s, np);
    }
}

// ======================= gates (pair-fused with hsum) =======================
__global__ void leafpair_k() {
    int idx = blockIdx.x * blockDim.x + threadIdx.x;  // 32*128*512
    int f = idx & 511, r = idx >> 9;   // r = b*128 + j
    int b = r >> 7, j = r & 127;
    float hs = 0.f;
    #pragma unroll
    for (int t = 0; t < 2; t++) {
        int node = 255 + 2 * j + t;
        size_t io = ((size_t)b * NN + node) * F3;
        float cn = sigf(g_fe_iou[io + f]) * fmaxf(g_fe_iou[io + 1024 + f], 0.f);
        float hn = sigf(g_fe_iou[io + 512 + f]) * tanhf(cn);
        size_t ho = ((size_t)b * NN + node) * F_ + f;
        g_c[ho] = cn;
        g_h[ho] = hn;
        split_bf(hn, g_hh[ho], g_hl[ho]);
        hs += hn;
    }
    split_bf(hs, g_hsh[(size_t)r * F_ + f], g_hsl[(size_t)r * F_ + f]);
}

__global__ void gatepair_k(int s, int np, int total) {
    int idx = blockIdx.x * blockDim.x + threadIdx.x;
    if (idx >= total) return;
    int f = idx & 511, r = idx >> 9;   // r = b*half + j
    int half = np >> 1;
    int b = r / half, j = r - b * half;
    float hs = 0.f;
    #pragma unroll
    for (int t = 0; t < 2; t++) {
        int pl = 2 * j + t;
        int rr = b * np + pl;
        int node = s + pl;
        size_t io = (size_t)rr * F3;
        float csum = g_fc[(size_t)(2 * rr) * F_ + f] + g_fc[(size_t)(2 * rr + 1) * F_ + f];
        float cn = sigf(g_iou[io + f]) * fmaxf(g_iou[io + 1024 + f], 0.f) + csum;
        float hn = sigf(g_iou[io + 512 + f]) * tanhf(cn);
        size_t ho = ((size_t)b * NN + node) * F_ + f;
        g_c[ho] = cn;
        g_h[ho] = hn;
        split_bf(hn, g_hh[ho], g_hl[ho]);
        hs += hn;
    }
    split_bf(hs, g_hsh[(size_t)r * F_ + f], g_hsl[(size_t)r * F_ + f]);
}

__global__ void gateroot_k() {
    int idx = blockIdx.x * blockDim.x + threadIdx.x;  // 32*512
    int f = idx & 511, b = idx >> 9;
    size_t io = (size_t)b * F3;
    float csum = g_fc[(size_t)(2 * b) * F_ + f] + g_fc[(size_t)(2 * b + 1) * F_ + f];
    float cn = sigf(g_iou[io + f]) * fmaxf(g_iou[io + 1024 + f], 0.f) + csum;
    float hn = sigf(g_iou[io + 512 + f]) * tanhf(cn);
    size_t ho = (size_t)b * NN * F_ + f;  // node 0
    g_c[ho] = cn;
    g_h[ho] = hn;
}

// ======================= readout =======================
__global__ void rscore_k() {
    int gw = (blockIdx.x * blockDim.x + threadIdx.x) >> 5;
    int lane = threadIdx.x & 31;
    if (gw >= B_ * NN) return;
    int b = gw / NN;
    const float4* hp = (const float4*)(g_h + (size_t)gw * F_);
    const float4* ep = (const float4*)(g_eforw + b * F_);
    float s = 0.f;
    for (int t = lane; t < 128; t += 32) {
        float4 h = hp[t], e = ep[t];
        s += h.x * e.x + h.y * e.y + h.z * e.z + h.w * e.w;
    }
    #pragma unroll
    for (int off = 16; off; off >>= 1) s += __shfl_xor_sync(0xffffffffu, s, off);
    if (!lane) g_r[b * 512 + (gw - b * NN)] = s;
}

__global__ void final_k(float* __restrict__ out) {
    __shared__ float red[128];
    __shared__ float pr[NN];
    int b = blockIdx.y, tid = threadIdx.x;
    float mx = -1e30f;
    for (int i = tid; i < NN; i += 128) mx = fmaxf(mx, g_r[b * 512 + i]);
    red[tid] = mx;
    __syncthreads();
    for (int o = 64; o; o >>= 1) {
        if (tid < o) red[tid] = fmaxf(red[tid], red[tid + o]);
        __syncthreads();
    }
    mx = red[0];
    __syncthreads();
    float sm = 0.f;
    for (int i = tid; i < NN; i += 128) {
        float e = expf(g_r[b * 512 + i] - mx);
        pr[i] = e;
        sm += e;
    }
    red[tid] = sm;
    __syncthreads();
    for (int o = 64; o; o >>= 1) {
        if (tid < o) red[tid] += red[tid + o];
        __syncthreads();
    }
    float inv = 1.f / red[0];
    __syncthreads();
    int f = blockIdx.x * 128 + tid;
    float acc = 0.f;
    for (int i = 0; i < NN; i++) acc += pr[i] * g_h[((size_t)b * NN + i) * F_ + f];
    out[b * F_ + f] = acc * inv;
}

// ======================= launcher =======================
extern "C" void kernel_launch(void* const* d_in, const int* in_sizes, int n_in,
                              void* d_out, int out_size) {
    const float* feat     = (const float*)d_in[0];
    const float* eh       = (const float*)d_in[5];
    const float* Wn       = (const float*)d_in[6];
    const float* Wf       = (const float*)d_in[7];
    const float* W_iou    = (const float*)d_in[8];
    const float* W_fe_iou = (const float*)d_in[9];
    const float* b_fe_iou = (const float*)d_in[10];
    const float* W_f      = (const float*)d_in[11];
    const float* W_fe_f   = (const float*)d_in[12];
    const float* b_fe_f   = (const float*)d_in[13];
    float* out = (float*)d_out;

    static bool attr_done = false;
    if (!attr_done) {
        cudaFuncSetAttribute(gemm_hmma<0>, cudaFuncAttributeMaxDynamicSharedMemorySize, SMEM_TOT);
        cudaFuncSetAttribute(gemm_hmma<1>, cudaFuncAttributeMaxDynamicSharedMemorySize, SMEM_TOT);
        cudaFuncSetAttribute(level_k, cudaFuncAttributeMaxDynamicSharedMemorySize, SMEM_TOT);
        attr_done = true;
    }

    conv_all<<<8192, 256>>>(W_fe_iou, W_fe_f, W_f, W_iou);

    enode_k<<<dim3(64, 32, 2), 256>>>(eh, Wn, Wf);
    scores_k<<<2044, 256>>>(feat);
    feat2_k<<<dim3(NN, B_), 256>>>(feat);

    // fe_iou: M = 16352, N = 1536
    gemm_hmma<0><<<dim3(12, 128), 256, SMEM_TOT>>>(b_fe_iou, 16352);
    // ff: M = 8160, N = 512
    gemm_hmma<1><<<dim3(4, 64), 256, SMEM_TOT>>>(b_fe_f, 8160);

    leafpair_k<<<(B_ * 128 * F_) / 256, 256>>>();

    for (int n = 1; n <= 8; n++) {
        int np = 1 << (8 - n);
        int s = np - 1;
        int Mf = B_ * 2 * np;
        int Mi = B_ * np;
        int yF = (Mf + 127) / 128;
        int yI = (Mi + 127) / 128;
        level_k<<<4 * yF + 12 * yI, 256, SMEM_TOT>>>(s, np, yF, Mf, Mi);
        if (np > 1) {
            int total = B_ * (np >> 1) * F_;
            gatepair_k<<<(total + 255) / 256, 256>>>(s, np, total);
        } else {
            gateroot_k<<<(B_ * F_) / 256, 256>>>();
        }
    }

    rscore_k<<<2044, 256>>>();
    final_k<<<dim3(4, B_), 128>>>(out);
}

// round 6
// speedup vs baseline: 4.0371x; 1.0430x over previous
#include <cuda_runtime.h>
#include <cuda_bf16.h>
#include <math.h>
#include <cstdint>

#define B_ 32
#define NN 511
#define F_ 512
#define F3 1536

// ======================= scratch (static device globals) =======================
static __device__ __align__(16) float g_enode[B_ * F_];
static __device__ __align__(16) float g_eforw[B_ * F_];
static __device__ __align__(16) float g_scores[B_ * 512];
static __device__ __align__(16) float g_fe_iou[(size_t)B_ * NN * F3];
static __device__ __align__(16) float g_ff[(size_t)B_ * 255 * F_];
static __device__ __align__(16) float g_h[(size_t)B_ * NN * F_];
static __device__ __align__(16) float g_c[(size_t)B_ * NN * F_];
static __device__ __align__(16) float g_fc[(size_t)B_ * 256 * F_];
static __device__ __align__(16) float g_iou[(size_t)B_ * 128 * F3];
static __device__ __align__(16) float g_r[B_ * 512];
// bf16 hi/lo activation pairs
static __device__ __align__(16) __nv_bfloat16 g_f2h[(size_t)B_ * NN * F_];
static __device__ __align__(16) __nv_bfloat16 g_f2l[(size_t)B_ * NN * F_];
static __device__ __align__(16) __nv_bfloat16 g_hh[(size_t)B_ * NN * F_];
static __device__ __align__(16) __nv_bfloat16 g_hl[(size_t)B_ * NN * F_];
static __device__ __align__(16) __nv_bfloat16 g_hsh[(size_t)B_ * 128 * F_];
static __device__ __align__(16) __nv_bfloat16 g_hsl[(size_t)B_ * 128 * F_];
// bf16 hi/lo weights
static __device__ __align__(16) __nv_bfloat16 g_wfeiou_h[F3 * F_], g_wfeiou_l[F3 * F_];
static __device__ __align__(16) __nv_bfloat16 g_wfef_h[F_ * F_],  g_wfef_l[F_ * F_];
static __device__ __align__(16) __nv_bfloat16 g_wf_h[F_ * F_],    g_wf_l[F_ * F_];
static __device__ __align__(16) __nv_bfloat16 g_wiou_h[F3 * F_],  g_wiou_l[F3 * F_];

__device__ __forceinline__ float sigf(float x) { return 1.f / (1.f + expf(-x)); }
__device__ __forceinline__ void split_bf(float x, __nv_bfloat16& h, __nv_bfloat16& l) {
    h = __float2bfloat16(x);
    l = __float2bfloat16(x - __bfloat162float(h));
}

__device__ __forceinline__ uint32_t smem_u32(const void* p) {
    uint32_t a;
    asm("{ .reg .u64 t; cvta.to.shared.u64 t, %1; cvt.u32.u64 %0, t; }" : "=r"(a) : "l"(p));
    return a;
}

#define CP16(dst, src) \
    asm volatile("cp.async.cg.shared.global [%0], [%1], 16;" :: "r"(dst), "l"(src) : "memory")
#define CP_COMMIT() asm volatile("cp.async.commit_group;" ::: "memory")
template <int N>
__device__ __forceinline__ void cp_wait() {
    asm volatile("cp.async.wait_group %0;" :: "n"(N) : "memory");
}

__device__ __forceinline__ void mma16816(float* c, const uint32_t* a, const uint32_t* b) {
    asm volatile(
        "mma.sync.aligned.m16n8k16.row.col.f32.bf16.bf16.f32 "
        "{%0,%1,%2,%3}, {%4,%5,%6,%7}, {%8,%9}, {%0,%1,%2,%3};"
        : "+f"(c[0]), "+f"(c[1]), "+f"(c[2]), "+f"(c[3])
        : "r"(a[0]), "r"(a[1]), "r"(a[2]), "r"(a[3]), "r"(b[0]), "r"(b[1]));
}

__device__ __forceinline__ void ldsm4(uint32_t& r0, uint32_t& r1, uint32_t& r2, uint32_t& r3,
                                      uint32_t addr) {
    asm volatile("ldmatrix.sync.aligned.m8n8.x4.shared.b16 {%0,%1,%2,%3}, [%4];"
                 : "=r"(r0), "=r"(r1), "=r"(r2), "=r"(r3) : "r"(addr));
}

// ======================= small kernels =======================
__global__ void conv_all(const float* __restrict__ s0, const float* __restrict__ s1,
                         const float* __restrict__ s2, const float* __restrict__ s3) {
    int i = blockIdx.x * 256 + threadIdx.x;  // total 2097152
    if (i < 786432) {
        split_bf(s0[i], g_wfeiou_h[i], g_wfeiou_l[i]);
    } else if (i < 1048576) {
        int j = i - 786432;
        split_bf(s1[j], g_wfef_h[j], g_wfef_l[j]);
    } else if (i < 1310720) {
        int j = i - 1048576;
        split_bf(s2[j], g_wf_h[j], g_wf_l[j]);
    } else {
        int j = i - 1310720;
        split_bf(s3[j], g_wiou_h[j], g_wiou_l[j]);
    }
}

__global__ void enode_k(const float* __restrict__ eh, const float* __restrict__ Wn,
                        const float* __restrict__ Wf) {
    int warp = threadIdx.x >> 5, lane = threadIdx.x & 31;
    int j = blockIdx.x * 8 + warp, b = blockIdx.y;
    const float* W = blockIdx.z ? Wf : Wn;
    float* o = blockIdx.z ? g_eforw : g_enode;
    const float4* wr = (const float4*)(W + (size_t)j * 1024);
    const float4* er = (const float4*)(eh + (size_t)b * 1024);
    float s = 0.f;
    for (int t = lane; t < 256; t += 32) {
        float4 w = wr[t], e = er[t];
        s += w.x * e.x + w.y * e.y + w.z * e.z + w.w * e.w;
    }
    #pragma unroll
    for (int off = 16; off; off >>= 1) s += __shfl_xor_sync(0xffffffffu, s, off);
    if (!lane) o[b * F_ + j] = s;
}

__global__ void scores_k(const float* __restrict__ feat) {
    int gw = (blockIdx.x * blockDim.x + threadIdx.x) >> 5;
    int lane = threadIdx.x & 31;
    if (gw >= B_ * NN) return;
    int b = gw / NN;
    const float4* fr = (const float4*)(feat + (size_t)gw * F_);
    const float4* er = (const float4*)(g_enode + b * F_);
    float s = 0.f;
    for (int t = lane; t < 128; t += 32) {
        float4 f = fr[t], e = er[t];
        s += f.x * e.x + f.y * e.y + f.z * e.z + f.w * e.w;
    }
    #pragma unroll
    for (int off = 16; off; off >>= 1) s += __shfl_xor_sync(0xffffffffu, s, off);
    if (!lane) g_scores[b * 512 + (gw - b * NN)] = s;
}

// ---------------- streaming feat2: rolling 4-row window ----------------
// grid (8 node-chunks, B_, 4 f-chunks), 128 threads. out[i] = sum_k p[i][k]*feat[i+k]
__global__ void __launch_bounds__(128)
feat2_k(const float* __restrict__ feat) {
    __shared__ float pr[64][4];
    const int ic = blockIdx.x, b = blockIdx.y, fch = blockIdx.z;
    const int tid = threadIdx.x;
    const int start = ic * 64;

    if (tid < 64) {
        int i = start + tid;
        if (i < NN) {
            int cnt = min(i + 3, NN - 1) - i + 1;
            float sc[4], mx = -1e30f;
            #pragma unroll
            for (int k = 0; k < 4; k++) {
                sc[k] = (k < cnt) ? g_scores[b * 512 + i + k] : -1e30f;
                mx = fmaxf(mx, sc[k]);
            }
            float sum = 0.f;
            #pragma unroll
            for (int k = 0; k < 4; k++) {
                sc[k] = (k < cnt) ? expf(sc[k] - mx) : 0.f;
                sum += sc[k];
            }
            float inv = 1.f / sum;
            #pragma unroll
            for (int k = 0; k < 4; k++) pr[tid][k] = sc[k] * inv;
        }
    }
    __syncthreads();

    const int f = fch * 128 + tid;
    const float* fb = feat + ((size_t)b * NN) * F_ + f;
    float r0 = fb[(size_t)min(start, NN - 1) * F_];
    float r1 = fb[(size_t)min(start + 1, NN - 1) * F_];
    float r2 = fb[(size_t)min(start + 2, NN - 1) * F_];
    size_t obase = ((size_t)b * NN + start) * F_ + f;
    const int nout = min(64, NN - start);
    for (int j = 0; j < nout; j++) {
        int i = start + j;
        float r3 = fb[(size_t)min(i + 3, NN - 1) * F_];
        float a = pr[j][0] * r0 + pr[j][1] * r1 + pr[j][2] * r2 + pr[j][3] * r3;
        split_bf(a, g_f2h[obase], g_f2l[obase]);
        obase += F_;
        r0 = r1; r1 = r2; r2 = r3;
    }
}

// ======================= HMMA GEMM core (bf16 hi/lo 3-pass, fp32 acc) =======================
// Block tile 128x128x32, 8 warps (2M x 4N), warp tile 64x32, ldmatrix fragments.
// MODE 0: fe_iou = feat2 @ W_fe_iou^T + bias
// MODE 1: ff     = feat2[parents] @ W_fe_f^T + bias
// MODE 2: fc     = sigmoid(h[child] @ W_f^T + ff[parent]) * c[child]
// MODE 3: iou    = hsum @ W_iou^T + fe_iou[parent]
#define TILE_B 10240
#define STAGE_B (4 * TILE_B)
#define SMEM_TOT (2 * STAGE_B)

template <int MODE>
__device__ __forceinline__ void gemm_core(char* smem, int bm, int bn,
                                          const float* __restrict__ bias,
                                          int M, int s, int np) {
    const uint32_t sb = smem_u32(smem);
    const int tid = threadIdx.x;
    const int warp = tid >> 5, lane = tid & 31;
    const int wm = warp >> 2, wn = warp & 3;
    const int qrow = lane >> 2, qcol = (lane & 3) * 2;

    const __nv_bfloat16 *Ah, *Al, *Wh, *Wl;
    if (MODE == 0) { Ah = g_f2h; Al = g_f2l; Wh = g_wfeiou_h; Wl = g_wfeiou_l; }
    else if (MODE == 1) { Ah = g_f2h; Al = g_f2l; Wh = g_wfef_h; Wl = g_wfef_l; }
    else if (MODE == 2) { Ah = g_hh; Al = g_hl; Wh = g_wf_h; Wl = g_wf_l; }
    else { Ah = g_hsh; Al = g_hsl; Wh = g_wiou_h; Wl = g_wiou_l; }

    // --- cp.async geometry: each thread covers 2 rows (row0, row0+64), one 16B quad ---
    const int quad = tid & 3;
    const int row0 = tid >> 2;
    int ar0, ar1;
    {
        int rA = min(bm + row0, M - 1);
        int rB = min(bm + row0 + 64, M - 1);
        if (MODE == 0 || MODE == 3) { ar0 = rA; ar1 = rB; }
        else if (MODE == 1) {
            int b0 = rA / 255; ar0 = b0 * NN + (rA - b0 * 255);
            int b1 = rB / 255; ar1 = b1 * NN + (rB - b1 * 255);
        } else {
            int two = 2 * np;
            int b0 = rA / two; ar0 = b0 * NN + 2 * s + 1 + (rA - b0 * two);
            int b1 = rB / two; ar1 = b1 * NN + 2 * s + 1 + (rB - b1 * two);
        }
    }
    const int a00 = ar0 * F_ + quad * 8;
    const int a01 = ar1 * F_ + quad * 8;
    const int w00 = (bn + row0) * F_ + quad * 8;
    const int w01 = (bn + row0 + 64) * F_ + quad * 8;
    const uint32_t d0 = (uint32_t)(row0 * 80 + quad * 16);
    const uint32_t d1 = d0 + 64 * 80;

    // --- ldmatrix lane offsets ---
    const uint32_t a_l = (uint32_t)((wm * 64 + (lane & 15)) * 80 + (lane >> 4) * 16);
    const uint32_t b_l = (uint32_t)((wn * 32 + ((lane >> 4) & 1) * 8 + (lane & 7)) * 80 +
                                    ((lane >> 3) & 1) * 16);

#define LOAD_CHUNK(cidx, stgi) do {                                        \
    int k0 = (cidx) * 32;                                                  \
    uint32_t s0a = sb + (stgi) * STAGE_B;                                  \
    CP16(s0a + d0,              Ah + a00 + k0);                            \
    CP16(s0a + d1,              Ah + a01 + k0);                            \
    CP16(s0a + TILE_B + d0,     Al + a00 + k0);                            \
    CP16(s0a + TILE_B + d1,     Al + a01 + k0);                            \
    CP16(s0a + 2 * TILE_B + d0, Wh + w00 + k0);                            \
    CP16(s0a + 2 * TILE_B + d1, Wh + w01 + k0);                            \
    CP16(s0a + 3 * TILE_B + d0, Wl + w00 + k0);                            \
    CP16(s0a + 3 * TILE_B + d1, Wl + w01 + k0);                            \
    CP_COMMIT();                                                          \
} while (0)

    float acc[4][4][4] = {};

    LOAD_CHUNK(0, 0);

    for (int c = 0; c < 16; c++) {
        if (c < 15) {
            LOAD_CHUNK(c + 1, (c + 1) & 1);
            cp_wait<1>();
        } else {
            cp_wait<0>();
        }
        __syncthreads();

        const uint32_t stg = sb + (c & 1) * STAGE_B;
        #pragma unroll
        for (int kk = 0; kk < 2; kk++) {
            uint32_t ah[4][4], al[4][4], bh[2][4], bl[2][4];
            #pragma unroll
            for (int mf = 0; mf < 4; mf++) {
                uint32_t aaddr = stg + a_l + mf * 1280 + kk * 32;
                ldsm4(ah[mf][0], ah[mf][1], ah[mf][2], ah[mf][3], aaddr);
                ldsm4(al[mf][0], al[mf][1], al[mf][2], al[mf][3], aaddr + TILE_B);
            }
            #pragma unroll
            for (int p = 0; p < 2; p++) {
                uint32_t baddr = stg + 2 * TILE_B + b_l + p * 1280 + kk * 32;
                ldsm4(bh[p][0], bh[p][1], bh[p][2], bh[p][3], baddr);
                ldsm4(bl[p][0], bl[p][1], bl[p][2], bl[p][3], baddr + TILE_B);
            }
            #pragma unroll
            for (int mf = 0; mf < 4; mf++)
                #pragma unroll
                for (int p = 0; p < 2; p++)
                    #pragma unroll
                    for (int q = 0; q < 2; q++) {
                        int nf = p * 2 + q;
                        mma16816(acc[mf][nf], ah[mf], &bh[p][2 * q]);
                        mma16816(acc[mf][nf], ah[mf], &bl[p][2 * q]);
                        mma16816(acc[mf][nf], al[mf], &bh[p][2 * q]);
                    }
        }
        __syncthreads();
    }
#undef LOAD_CHUNK

    // --- epilogue ---
    #pragma unroll
    for (int mf = 0; mf < 4; mf++) {
        #pragma unroll
        for (int half = 0; half < 2; half++) {
            int m = bm + wm * 64 + mf * 16 + qrow + half * 8;
            if (m >= M) continue;
            int b = 0, node = 0, p = 0;
            if (MODE == 2) {
                int two = 2 * np;
                b = m / two;
                int cl = m - b * two;
                node = 2 * s + 1 + cl;
                p = s + (cl >> 1);
            } else if (MODE == 3) {
                b = m / np;
                p = s + (m - b * np);
            }
            #pragma unroll
            for (int nf = 0; nf < 4; nf++) {
                int n = bn + wn * 32 + nf * 8 + qcol;
                float2 v = make_float2(acc[mf][nf][half * 2], acc[mf][nf][half * 2 + 1]);
                if (MODE == 0) {
                    float2 bi = *(const float2*)(bias + n);
                    v.x += bi.x; v.y += bi.y;
                    *(float2*)(g_fe_iou + (size_t)m * F3 + n) = v;
                } else if (MODE == 1) {
                    float2 bi = *(const float2*)(bias + n);
                    v.x += bi.x; v.y += bi.y;
                    *(float2*)(g_ff + (size_t)m * F_ + n) = v;
                } else if (MODE == 2) {
                    float2 ffv = *(const float2*)(g_ff + ((size_t)b * 255 + p) * F_ + n);
                    float2 cv  = *(const float2*)(g_c + ((size_t)b * NN + node) * F_ + n);
                    float2 o;
                    o.x = sigf(v.x + ffv.x) * cv.x;
                    o.y = sigf(v.y + ffv.y) * cv.y;
                    *(float2*)(g_fc + (size_t)m * F_ + n) = o;
                } else {
                    float2 fe = *(const float2*)(g_fe_iou + ((size_t)b * NN + p) * F3 + n);
                    v.x += fe.x; v.y += fe.y;
                    *(float2*)(g_iou + (size_t)m * F3 + n) = v;
                }
            }
        }
    }
}

// combined front GEMMs: fe_iou (12x128 tiles) then ff (4x64 tiles)
__global__ void __launch_bounds__(256)
front_k(const float* __restrict__ b_iou, const float* __restrict__ b_f) {
    extern __shared__ char smem[];
    int bx = blockIdx.x;
    if (bx < 1536) {
        gemm_core<0>(smem, (bx / 12) * 128, (bx % 12) * 128, b_iou, 16352, 0, 0);
    } else {
        bx -= 1536;
        gemm_core<1>(smem, (bx >> 2) * 128, (bx & 3) * 128, b_f, 8160, 0, 0);
    }
}

// fused per-level kernel: fc blocks first, iou blocks after
__global__ void __launch_bounds__(256)
level_k(int s, int np, int yF, int Mf, int Mi) {
    extern __shared__ char smem[];
    int bx = blockIdx.x;
    if (bx < 4 * yF) {
        gemm_core<2>(smem, (bx >> 2) * 128, (bx & 3) * 128, nullptr, Mf, s, np);
    } else {
        bx -= 4 * yF;
        gemm_core<3>(smem, (bx / 12) * 128, (bx % 12) * 128, nullptr, Mi, s, np);
    }
}

// ======================= gates (pair-fused with hsum) =======================
__global__ void leafpair_k() {
    int idx = blockIdx.x * blockDim.x + threadIdx.x;  // 32*128*512
    int f = idx & 511, r = idx >> 9;   // r = b*128 + j
    int b = r >> 7, j = r & 127;
    float hs = 0.f;
    #pragma unroll
    for (int t = 0; t < 2; t++) {
        int node = 255 + 2 * j + t;
        size_t io = ((size_t)b * NN + node) * F3;
        float cn = sigf(g_fe_iou[io + f]) * fmaxf(g_fe_iou[io + 1024 + f], 0.f);
        float hn = sigf(g_fe_iou[io + 512 + f]) * tanhf(cn);
        size_t ho = ((size_t)b * NN + node) * F_ + f;
        g_c[ho] = cn;
        g_h[ho] = hn;
        split_bf(hn, g_hh[ho], g_hl[ho]);
        hs += hn;
    }
    split_bf(hs, g_hsh[(size_t)r * F_ + f], g_hsl[(size_t)r * F_ + f]);
}

__global__ void gatepair_k(int s, int np, int total) {
    int idx = blockIdx.x * blockDim.x + threadIdx.x;
    if (idx >= total) return;
    int f = idx & 511, r = idx >> 9;   // r = b*half + j
    int half = np >> 1;
    int b = r / half, j = r - b * half;
    float hs = 0.f;
    #pragma unroll
    for (int t = 0; t < 2; t++) {
        int pl = 2 * j + t;
        int rr = b * np + pl;
        int node = s + pl;
        size_t io = (size_t)rr * F3;
        float csum = g_fc[(size_t)(2 * rr) * F_ + f] + g_fc[(size_t)(2 * rr + 1) * F_ + f];
        float cn = sigf(g_iou[io + f]) * fmaxf(g_iou[io + 1024 + f], 0.f) + csum;
        float hn = sigf(g_iou[io + 512 + f]) * tanhf(cn);
        size_t ho = ((size_t)b * NN + node) * F_ + f;
        g_c[ho] = cn;
        g_h[ho] = hn;
        split_bf(hn, g_hh[ho], g_hl[ho]);
        hs += hn;
    }
    split_bf(hs, g_hsh[(size_t)r * F_ + f], g_hsl[(size_t)r * F_ + f]);
}

__global__ void gateroot_k() {
    int idx = blockIdx.x * blockDim.x + threadIdx.x;  // 32*512
    int f = idx & 511, b = idx >> 9;
    size_t io = (size_t)b * F3;
    float csum = g_fc[(size_t)(2 * b) * F_ + f] + g_fc[(size_t)(2 * b + 1) * F_ + f];
    float cn = sigf(g_iou[io + f]) * fmaxf(g_iou[io + 1024 + f], 0.f) + csum;
    float hn = sigf(g_iou[io + 512 + f]) * tanhf(cn);
    size_t ho = (size_t)b * NN * F_ + f;  // node 0
    g_c[ho] = cn;
    g_h[ho] = hn;
}

// ======================= readout =======================
__global__ void rscore_k() {
    int gw = (blockIdx.x * blockDim.x + threadIdx.x) >> 5;
    int lane = threadIdx.x & 31;
    if (gw >= B_ * NN) return;
    int b = gw / NN;
    const float4* hp = (const float4*)(g_h + (size_t)gw * F_);
    const float4* ep = (const float4*)(g_eforw + b * F_);
    float s = 0.f;
    for (int t = lane; t < 128; t += 32) {
        float4 h = hp[t], e = ep[t];
        s += h.x * e.x + h.y * e.y + h.z * e.z + h.w * e.w;
    }
    #pragma unroll
    for (int off = 16; off; off >>= 1) s += __shfl_xor_sync(0xffffffffu, s, off);
    if (!lane) g_r[b * 512 + (gw - b * NN)] = s;
}

__global__ void final_k(float* __restrict__ out) {
    __shared__ float red[128];
    __shared__ float pr[NN];
    int b = blockIdx.y, tid = threadIdx.x;
    float mx = -1e30f;
    for (int i = tid; i < NN; i += 128) mx = fmaxf(mx, g_r[b * 512 + i]);
    red[tid] = mx;
    __syncthreads();
    for (int o = 64; o; o >>= 1) {
        if (tid < o) red[tid] = fmaxf(red[tid], red[tid + o]);
        __syncthreads();
    }
    mx = red[0];
    __syncthreads();
    float sm = 0.f;
    for (int i = tid; i < NN; i += 128) {
        float e = expf(g_r[b * 512 + i] - mx);
        pr[i] = e;
        sm += e;
    }
    red[tid] = sm;
    __syncthreads();
    for (int o = 64; o; o >>= 1) {
        if (tid < o) red[tid] += red[tid + o];
        __syncthreads();
    }
    float inv = 1.f / red[0];
    __syncthreads();
    int f = blockIdx.x * 128 + tid;
    float acc = 0.f;
    for (int i = 0; i < NN; i++) acc += pr[i] * g_h[((size_t)b * NN + i) * F_ + f];
    out[b * F_ + f] = acc * inv;
}

// ======================= launcher =======================
extern "C" void kernel_launch(void* const* d_in, const int* in_sizes, int n_in,
                              void* d_out, int out_size) {
    const float* feat     = (const float*)d_in[0];
    const float* eh       = (const float*)d_in[5];
    const float* Wn       = (const float*)d_in[6];
    const float* Wf       = (const float*)d_in[7];
    const float* W_iou    = (const float*)d_in[8];
    const float* W_fe_iou = (const float*)d_in[9];
    const float* b_fe_iou = (const float*)d_in[10];
    const float* W_f      = (const float*)d_in[11];
    const float* W_fe_f   = (const float*)d_in[12];
    const float* b_fe_f   = (const float*)d_in[13];
    float* out = (float*)d_out;

    static bool attr_done = false;
    if (!attr_done) {
        cudaFuncSetAttribute(front_k, cudaFuncAttributeMaxDynamicSharedMemorySize, SMEM_TOT);
        cudaFuncSetAttribute(level_k, cudaFuncAttributeMaxDynamicSharedMemorySize, SMEM_TOT);
        attr_done = true;
    }

    conv_all<<<8192, 256>>>(W_fe_iou, W_fe_f, W_f, W_iou);

    enode_k<<<dim3(64, 32, 2), 256>>>(eh, Wn, Wf);
    scores_k<<<2044, 256>>>(feat);
    feat2_k<<<dim3(8, B_, 4), 128>>>(feat);

    // fe_iou (M=16352,N=1536) + ff (M=8160,N=512) in one launch
    front_k<<<1536 + 256, 256, SMEM_TOT>>>(b_fe_iou, b_fe_f);

    leafpair_k<<<(B_ * 128 * F_) / 256, 256>>>();

    for (int n = 1; n <= 8; n++) {
        int np = 1 << (8 - n);
        int s = np - 1;
        int Mf = B_ * 2 * np;
        int Mi = B_ * np;
        int yF = (Mf + 127) / 128;
        int yI = (Mi + 127) / 128;
        level_k<<<4 * yF + 12 * yI, 256, SMEM_TOT>>>(s, np, yF, Mf, Mi);
        if (np > 1) {
            int total = B_ * (np >> 1) * F_;
            gatepair_k<<<(total + 255) / 256, 256>>>(s, np, total);
        } else {
            gateroot_k<<<(B_ * F_) / 256, 256>>>();
        }
    }

    rscore_k<<<2044, 256>>>();
    final_k<<<dim3(4, B_), 128>>>(out);
}

// round 9
// speedup vs baseline: 5.7894x; 1.4341x over previous
#include <cuda_runtime.h>
#include <cuda_fp16.h>
#include <math.h>
#include <cstdint>

#define B_ 32
#define NN 511
#define F_ 512
#define F3 1536

// ======================= scratch (static device globals) =======================
static __device__ __align__(16) float g_enode[B_ * F_];
static __device__ __align__(16) float g_eforw[B_ * F_];
static __device__ __align__(16) float g_scores[B_ * 512];
static __device__ __align__(16) float g_fe_iou[(size_t)B_ * NN * F3];
static __device__ __align__(16) float g_ff[(size_t)B_ * 255 * F_];
static __device__ __align__(16) float g_h[(size_t)B_ * NN * F_];
static __device__ __align__(16) float g_c[(size_t)B_ * NN * F_];
static __device__ __align__(16) float g_fc[(size_t)B_ * 256 * F_];
static __device__ __align__(16) float g_iou[(size_t)B_ * 128 * F3];
static __device__ __align__(16) float g_r[B_ * 512];
// fp16 activations (single precision-rounded copy)
static __device__ __align__(16) __half g_f2[(size_t)B_ * NN * F_];
static __device__ __align__(16) __half g_ha[(size_t)B_ * NN * F_];
static __device__ __align__(16) __half g_hs[(size_t)B_ * 128 * F_];
// fp16 hi/lo weights
static __device__ __align__(16) __half g_wfeiou_h[F3 * F_], g_wfeiou_l[F3 * F_];
static __device__ __align__(16) __half g_wfef_h[F_ * F_],  g_wfef_l[F_ * F_];
static __device__ __align__(16) __half g_wf_h[F_ * F_],    g_wf_l[F_ * F_];
static __device__ __align__(16) __half g_wiou_h[F3 * F_],  g_wiou_l[F3 * F_];

__device__ __forceinline__ float sigf(float x) { return 1.f / (1.f + expf(-x)); }
__device__ __forceinline__ void split_h(float x, __half& h, __half& l) {
    h = __float2half(x);
    l = __float2half(x - __half2float(h));
}

__device__ __forceinline__ uint32_t smem_u32(const void* p) {
    uint32_t a;
    asm("{ .reg .u64 t; cvta.to.shared.u64 t, %1; cvt.u32.u64 %0, t; }" : "=r"(a) : "l"(p));
    return a;
}

#define CP16(dst, src) \
    asm volatile("cp.async.cg.shared.global [%0], [%1], 16;" :: "r"(dst), "l"(src) : "memory")
#define CP_COMMIT() asm volatile("cp.async.commit_group;" ::: "memory")
template <int N>
__device__ __forceinline__ void cp_wait() {
    asm volatile("cp.async.wait_group %0;" :: "n"(N) : "memory");
}

__device__ __forceinline__ void mma16816(float* c, const uint32_t* a, const uint32_t* b) {
    asm volatile(
        "mma.sync.aligned.m16n8k16.row.col.f32.f16.f16.f32 "
        "{%0,%1,%2,%3}, {%4,%5,%6,%7}, {%8,%9}, {%0,%1,%2,%3};"
        : "+f"(c[0]), "+f"(c[1]), "+f"(c[2]), "+f"(c[3])
        : "r"(a[0]), "r"(a[1]), "r"(a[2]), "r"(a[3]), "r"(b[0]), "r"(b[1]));
}

__device__ __forceinline__ void ldsm4(uint32_t& r0, uint32_t& r1, uint32_t& r2, uint32_t& r3,
                                      uint32_t addr) {
    asm volatile("ldmatrix.sync.aligned.m8n8.x4.shared.b16 {%0,%1,%2,%3}, [%4];"
                 : "=r"(r0), "=r"(r1), "=r"(r2), "=r"(r3) : "r"(addr));
}

// ======================= small kernels =======================
__global__ void conv_all(const float* __restrict__ s0, const float* __restrict__ s1,
                         const float* __restrict__ s2, const float* __restrict__ s3) {
    int i = blockIdx.x * 256 + threadIdx.x;  // total 2097152
    if (i < 786432) {
        split_h(s0[i], g_wfeiou_h[i], g_wfeiou_l[i]);
    } else if (i < 1048576) {
        int j = i - 786432;
        split_h(s1[j], g_wfef_h[j], g_wfef_l[j]);
    } else if (i < 1310720) {
        int j = i - 1048576;
        split_h(s2[j], g_wf_h[j], g_wf_l[j]);
    } else {
        int j = i - 1310720;
        split_h(s3[j], g_wiou_h[j], g_wiou_l[j]);
    }
}

__global__ void enode_k(const float* __restrict__ eh, const float* __restrict__ Wn,
                        const float* __restrict__ Wf) {
    int warp = threadIdx.x >> 5, lane = threadIdx.x & 31;
    int j = blockIdx.x * 8 + warp, b = blockIdx.y;
    const float* W = blockIdx.z ? Wf : Wn;
    float* o = blockIdx.z ? g_eforw : g_enode;
    const float4* wr = (const float4*)(W + (size_t)j * 1024);
    const float4* er = (const float4*)(eh + (size_t)b * 1024);
    float s = 0.f;
    for (int t = lane; t < 256; t += 32) {
        float4 w = wr[t], e = er[t];
        s += w.x * e.x + w.y * e.y + w.z * e.z + w.w * e.w;
    }
    #pragma unroll
    for (int off = 16; off; off >>= 1) s += __shfl_xor_sync(0xffffffffu, s, off);
    if (!lane) o[b * F_ + j] = s;
}

__global__ void scores_k(const float* __restrict__ feat) {
    int gw = (blockIdx.x * blockDim.x + threadIdx.x) >> 5;
    int lane = threadIdx.x & 31;
    if (gw >= B_ * NN) return;
    int b = gw / NN;
    const float4* fr = (const float4*)(feat + (size_t)gw * F_);
    const float4* er = (const float4*)(g_enode + b * F_);
    float s = 0.f;
    for (int t = lane; t < 128; t += 32) {
        float4 f = fr[t], e = er[t];
        s += f.x * e.x + f.y * e.y + f.z * e.z + f.w * e.w;
    }
    #pragma unroll
    for (int off = 16; off; off >>= 1) s += __shfl_xor_sync(0xffffffffu, s, off);
    if (!lane) g_scores[b * 512 + (gw - b * NN)] = s;
}

// ---------------- streaming feat2: rolling 4-row window ----------------
__global__ void __launch_bounds__(128)
feat2_k(const float* __restrict__ feat) {
    __shared__ float pr[64][4];
    const int ic = blockIdx.x, b = blockIdx.y, fch = blockIdx.z;
    const int tid = threadIdx.x;
    const int start = ic * 64;

    if (tid < 64) {
        int i = start + tid;
        if (i < NN) {
            int cnt = min(i + 3, NN - 1) - i + 1;
            float sc[4], mx = -1e30f;
            #pragma unroll
            for (int k = 0; k < 4; k++) {
                sc[k] = (k < cnt) ? g_scores[b * 512 + i + k] : -1e30f;
                mx = fmaxf(mx, sc[k]);
            }
            float sum = 0.f;
            #pragma unroll
            for (int k = 0; k < 4; k++) {
                sc[k] = (k < cnt) ? expf(sc[k] - mx) : 0.f;
                sum += sc[k];
            }
            float inv = 1.f / sum;
            #pragma unroll
            for (int k = 0; k < 4; k++) pr[tid][k] = sc[k] * inv;
        }
    }
    __syncthreads();

    const int f = fch * 128 + tid;
    const float* fb = feat + ((size_t)b * NN) * F_ + f;
    float r0 = fb[(size_t)min(start, NN - 1) * F_];
    float r1 = fb[(size_t)min(start + 1, NN - 1) * F_];
    float r2 = fb[(size_t)min(start + 2, NN - 1) * F_];
    size_t obase = ((size_t)b * NN + start) * F_ + f;
    const int nout = min(64, NN - start);
    for (int j = 0; j < nout; j++) {
        int i = start + j;
        float r3 = fb[(size_t)min(i + 3, NN - 1) * F_];
        float a = pr[j][0] * r0 + pr[j][1] * r1 + pr[j][2] * r2 + pr[j][3] * r3;
        g_f2[obase] = __float2half(a);
        obase += F_;
        r0 = r1; r1 = r2; r2 = r3;
    }
}

// ======================= HMMA GEMM core (fp16 W-split 2-pass, fp32 acc) =======================
// Block tile 128x128x32, 8 warps (2M x 4N), warp tile 64x32, ldmatrix fragments.
// 3-stage cp.async pipeline, single __syncthreads per chunk.
// MODE 0: fe_iou = feat2 @ W_fe_iou^T + bias
// MODE 1: ff     = feat2[parents] @ W_fe_f^T + bias
// MODE 2: fc     = sigmoid(h[child] @ W_f^T + ff[parent]) * c[child]
// MODE 3: iou    = hsum @ W_iou^T + fe_iou[parent]
#define TILE_B 10240
#define STAGE_B (3 * TILE_B)
#define SMEM_TOT (3 * STAGE_B)

template <int MODE>
__device__ __forceinline__ void gemm_core(char* smem, int bm, int bn,
                                          const float* __restrict__ bias,
                                          int M, int s, int np) {
    const uint32_t sb = smem_u32(smem);
    const int tid = threadIdx.x;
    const int warp = tid >> 5, lane = tid & 31;
    const int wm = warp >> 2, wn = warp & 3;
    const int qrow = lane >> 2, qcol = (lane & 3) * 2;

    const __half *Aa, *Wh, *Wl;
    if (MODE == 0) { Aa = g_f2; Wh = g_wfeiou_h; Wl = g_wfeiou_l; }
    else if (MODE == 1) { Aa = g_f2; Wh = g_wfef_h; Wl = g_wfef_l; }
    else if (MODE == 2) { Aa = g_ha; Wh = g_wf_h; Wl = g_wf_l; }
    else { Aa = g_hs; Wh = g_wiou_h; Wl = g_wiou_l; }

    // --- cp.async geometry: each thread covers 2 rows (row0, row0+64), one 16B quad ---
    const int quad = tid & 3;
    const int row0 = tid >> 2;
    int ar0, ar1;
    {
        int rA = min(bm + row0, M - 1);
        int rB = min(bm + row0 + 64, M - 1);
        if (MODE == 0 || MODE == 3) { ar0 = rA; ar1 = rB; }
        else if (MODE == 1) {
            int b0 = rA / 255; ar0 = b0 * NN + (rA - b0 * 255);
            int b1 = rB / 255; ar1 = b1 * NN + (rB - b1 * 255);
        } else {
            int two = 2 * np;
            int b0 = rA / two; ar0 = b0 * NN + 2 * s + 1 + (rA - b0 * two);
            int b1 = rB / two; ar1 = b1 * NN + 2 * s + 1 + (rB - b1 * two);
        }
    }
    const int a00 = ar0 * F_ + quad * 8;
    const int a01 = ar1 * F_ + quad * 8;
    const int w00 = (bn + row0) * F_ + quad * 8;
    const int w01 = (bn + row0 + 64) * F_ + quad * 8;
    const uint32_t d0 = (uint32_t)(row0 * 80 + quad * 16);
    const uint32_t d1 = d0 + 64 * 80;

    // --- ldmatrix lane offsets ---
    const uint32_t a_l = (uint32_t)((wm * 64 + (lane & 15)) * 80 + (lane >> 4) * 16);
    const uint32_t b_l = (uint32_t)((wn * 32 + ((lane >> 4) & 1) * 8 + (lane & 7)) * 80 +
                                    ((lane >> 3) & 1) * 16);

#define LOAD_CHUNK(cidx, stgi) do {                                        \
    int k0 = (cidx) * 32;                                                  \
    uint32_t s0a = sb + (stgi) * STAGE_B;                                  \
    CP16(s0a + d0,              Aa + a00 + k0);                            \
    CP16(s0a + d1,              Aa + a01 + k0);                            \
    CP16(s0a + TILE_B + d0,     Wh + w00 + k0);                            \
    CP16(s0a + TILE_B + d1,     Wh + w01 + k0);                            \
    CP16(s0a + 2 * TILE_B + d0, Wl + w00 + k0);                            \
    CP16(s0a + 2 * TILE_B + d1, Wl + w01 + k0);                            \
    CP_COMMIT();                                                          \
} while (0)

    float acc[4][4][4] = {};

    LOAD_CHUNK(0, 0);
    LOAD_CHUNK(1, 1);

    int stg_idx = 0;
    for (int c = 0; c < 16; c++) {
        if (c < 15) cp_wait<1>(); else cp_wait<0>();
        __syncthreads();
        if (c < 14) {
            int ns = stg_idx + 2; if (ns >= 3) ns -= 3;
            LOAD_CHUNK(c + 2, ns);
        }

        const uint32_t stg = sb + stg_idx * STAGE_B;
        #pragma unroll
        for (int kk = 0; kk < 2; kk++) {
            uint32_t ah[4][4], bh[2][4], bl[2][4];
            #pragma unroll
            for (int mf = 0; mf < 4; mf++) {
                ldsm4(ah[mf][0], ah[mf][1], ah[mf][2], ah[mf][3],
                      stg + a_l + mf * 1280 + kk * 32);
            }
            #pragma unroll
            for (int p = 0; p < 2; p++) {
                uint32_t baddr = stg + TILE_B + b_l + p * 1280 + kk * 32;
                ldsm4(bh[p][0], bh[p][1], bh[p][2], bh[p][3], baddr);
                ldsm4(bl[p][0], bl[p][1], bl[p][2], bl[p][3], baddr + TILE_B);
            }
            #pragma unroll
            for (int mf = 0; mf < 4; mf++)
                #pragma unroll
                for (int p = 0; p < 2; p++)
                    #pragma unroll
                    for (int q = 0; q < 2; q++) {
                        int nf = p * 2 + q;
                        mma16816(acc[mf][nf], ah[mf], &bh[p][2 * q]);
                        mma16816(acc[mf][nf], ah[mf], &bl[p][2 * q]);
                    }
        }
        if (++stg_idx == 3) stg_idx = 0;
    }
#undef LOAD_CHUNK

    // --- epilogue ---
    #pragma unroll
    for (int mf = 0; mf < 4; mf++) {
        #pragma unroll
        for (int half = 0; half < 2; half++) {
            int m = bm + wm * 64 + mf * 16 + qrow + half * 8;
            if (m >= M) continue;
            int b = 0, node = 0, p = 0;
            if (MODE == 2) {
                int two = 2 * np;
                b = m / two;
                int cl = m - b * two;
                node = 2 * s + 1 + cl;
                p = s + (cl >> 1);
            } else if (MODE == 3) {
                b = m / np;
                p = s + (m - b * np);
            }
            #pragma unroll
            for (int nf = 0; nf < 4; nf++) {
                int n = bn + wn * 32 + nf * 8 + qcol;
                float2 v = make_float2(acc[mf][nf][half * 2], acc[mf][nf][half * 2 + 1]);
                if (MODE == 0) {
                    float2 bi = *(const float2*)(bias + n);
                    v.x += bi.x; v.y += bi.y;
                    *(float2*)(g_fe_iou + (size_t)m * F3 + n) = v;
                } else if (MODE == 1) {
                    float2 bi = *(const float2*)(bias + n);
                    v.x += bi.x; v.y += bi.y;
                    *(float2*)(g_ff + (size_t)m * F_ + n) = v;
                } else if (MODE == 2) {
                    float2 ffv = *(const float2*)(g_ff + ((size_t)b * 255 + p) * F_ + n);
                    float2 cv  = *(const float2*)(g_c + ((size_t)b * NN + node) * F_ + n);
                    float2 o;
                    o.x = sigf(v.x + ffv.x) * cv.x;
                    o.y = sigf(v.y + ffv.y) * cv.y;
                    *(float2*)(g_fc + (size_t)m * F_ + n) = o;
                } else {
                    float2 fe = *(const float2*)(g_fe_iou + ((size_t)b * NN + p) * F3 + n);
                    v.x += fe.x; v.y += fe.y;
                    *(float2*)(g_iou + (size_t)m * F3 + n) = v;
                }
            }
        }
    }
}

// combined front GEMMs: fe_iou (12-wide tiles) then ff (4-wide tiles)
__global__ void __launch_bounds__(256, 2)
front_k(const float* __restrict__ b_iou, const float* __restrict__ b_f) {
    extern __shared__ char smem[];
    int bx = blockIdx.x;
    if (bx < 1536) {
        gemm_core<0>(smem, (bx / 12) * 128, (bx % 12) * 128, b_iou, 16352, 0, 0);
    } else {
        bx -= 1536;
        gemm_core<1>(smem, (bx >> 2) * 128, (bx & 3) * 128, b_f, 8160, 0, 0);
    }
}

// fused per-level kernel: fc blocks first, iou blocks after
__global__ void __launch_bounds__(256, 2)
level_k(int s, int np, int yF, int Mf, int Mi) {
    extern __shared__ char smem[];
    int bx = blockIdx.x;
    if (bx < 4 * yF) {
        gemm_core<2>(smem, (bx >> 2) * 128, (bx & 3) * 128, nullptr, Mf, s, np);
    } else {
        bx -= 4 * yF;
        gemm_core<3>(smem, (bx / 12) * 128, (bx % 12) * 128, nullptr, Mi, s, np);
    }
}

// ======================= gates (pair-fused with hsum) =======================
__global__ void leafpair_k() {
    int idx = blockIdx.x * blockDim.x + threadIdx.x;  // 32*128*512
    int f = idx & 511, r = idx >> 9;   // r = b*128 + j
    int b = r >> 7, j = r & 127;
    float hs = 0.f;
    #pragma unroll
    for (int t = 0; t < 2; t++) {
        int node = 255 + 2 * j + t;
        size_t io = ((size_t)b * NN + node) * F3;
        float cn = sigf(g_fe_iou[io + f]) * fmaxf(g_fe_iou[io + 1024 + f], 0.f);
        float hn = sigf(g_fe_iou[io + 512 + f]) * tanhf(cn);
        size_t ho = ((size_t)b * NN + node) * F_ + f;
        g_c[ho] = cn;
        g_h[ho] = hn;
        g_ha[ho] = __float2half(hn);
        hs += hn;
    }
    g_hs[(size_t)r * F_ + f] = __float2half(hs);
}

__global__ void gatepair_k(int s, int np, int total) {
    int idx = blockIdx.x * blockDim.x + threadIdx.x;
    if (idx >= total) return;
    int f = idx & 511, r = idx >> 9;   // r = b*half + j
    int half = np >> 1;
    int b = r / half, j = r - b * half;
    float hs = 0.f;
    #pragma unroll
    for (int t = 0; t < 2; t++) {
        int pl = 2 * j + t;
        int rr = b * np + pl;
        int node = s + pl;
        size_t io = (size_t)rr * F3;
        float csum = g_fc[(size_t)(2 * rr) * F_ + f] + g_fc[(size_t)(2 * rr + 1) * F_ + f];
        float cn = sigf(g_iou[io + f]) * fmaxf(g_iou[io + 1024 + f], 0.f) + csum;
        float hn = sigf(g_iou[io + 512 + f]) * tanhf(cn);
        size_t ho = ((size_t)b * NN + node) * F_ + f;
        g_c[ho] = cn;
        g_h[ho] = hn;
        g_ha[ho] = __float2half(hn);
        hs += hn;
    }
    g_hs[(size_t)r * F_ + f] = __float2half(hs);
}

__global__ void gateroot_k() {
    int idx = blockIdx.x * blockDim.x + threadIdx.x;  // 32*512
    int f = idx & 511, b = idx >> 9;
    size_t io = (size_t)b * F3;
    float csum = g_fc[(size_t)(2 * b) * F_ + f] + g_fc[(size_t)(2 * b + 1) * F_ + f];
    float cn = sigf(g_iou[io + f]) * fmaxf(g_iou[io + 1024 + f], 0.f) + csum;
    float hn = sigf(g_iou[io + 512 + f]) * tanhf(cn);
    size_t ho = (size_t)b * NN * F_ + f;  // node 0
    g_c[ho] = cn;
    g_h[ho] = hn;
}

// ======================= readout =======================
__global__ void rscore_k() {
    int gw = (blockIdx.x * blockDim.x + threadIdx.x) >> 5;
    int lane = threadIdx.x & 31;
    if (gw >= B_ * NN) return;
    int b = gw / NN;
    const float4* hp = (const float4*)(g_h + (size_t)gw * F_);
    const float4* ep = (const float4*)(g_eforw + b * F_);
    float s = 0.f;
    for (int t = lane; t < 128; t += 32) {
        float4 h = hp[t], e = ep[t];
        s += h.x * e.x + h.y * e.y + h.z * e.z + h.w * e.w;
    }
    #pragma unroll
    for (int off = 16; off; off >>= 1) s += __shfl_xor_sync(0xffffffffu, s, off);
    if (!lane) g_r[b * 512 + (gw - b * NN)] = s;
}

__global__ void final_k(float* __restrict__ out) {
    __shared__ float red[128];
    __shared__ float pr[NN];
    int b = blockIdx.y, tid = threadIdx.x;
    float mx = -1e30f;
    for (int i = tid; i < NN; i += 128) mx = fmaxf(mx, g_r[b * 512 + i]);
    red[tid] = mx;
    __syncthreads();
    for (int o = 64; o; o >>= 1) {
        if (tid < o) red[tid] = fmaxf(red[tid], red[tid + o]);
        __syncthreads();
    }
    mx = red[0];
    __syncthreads();
    float sm = 0.f;
    for (int i = tid; i < NN; i += 128) {
        float e = expf(g_r[b * 512 + i] - mx);
        pr[i] = e;
        sm += e;
    }
    red[tid] = sm;
    __syncthreads();
    for (int o = 64; o; o >>= 1) {
        if (tid < o) red[tid] += red[tid + o];
        __syncthreads();
    }
    float inv = 1.f / red[0];
    __syncthreads();
    int f = blockIdx.x * 128 + tid;
    float acc = 0.f;
    for (int i = 0; i < NN; i++) acc += pr[i] * g_h[((size_t)b * NN + i) * F_ + f];
    out[b * F_ + f] = acc * inv;
}

// ======================= launcher =======================
extern "C" void kernel_launch(void* const* d_in, const int* in_sizes, int n_in,
                              void* d_out, int out_size) {
    const float* feat     = (const float*)d_in[0];
    const float* eh       = (const float*)d_in[5];
    const float* Wn       = (const float*)d_in[6];
    const float* Wf       = (const float*)d_in[7];
    const float* W_iou    = (const float*)d_in[8];
    const float* W_fe_iou = (const float*)d_in[9];
    const float* b_fe_iou = (const float*)d_in[10];
    const float* W_f      = (const float*)d_in[11];
    const float* W_fe_f   = (const float*)d_in[12];
    const float* b_fe_f   = (const float*)d_in[13];
    float* out = (float*)d_out;

    static bool attr_done = false;
    if (!attr_done) {
        cudaFuncSetAttribute(front_k, cudaFuncAttributeMaxDynamicSharedMemorySize, SMEM_TOT);
        cudaFuncSetAttribute(level_k, cudaFuncAttributeMaxDynamicSharedMemorySize, SMEM_TOT);
        attr_done = true;
    }

    conv_all<<<8192, 256>>>(W_fe_iou, W_fe_f, W_f, W_iou);

    enode_k<<<dim3(64, 32, 2), 256>>>(eh, Wn, Wf);
    scores_k<<<2044, 256>>>(feat);
    feat2_k<<<dim3(8, B_, 4), 128>>>(feat);

    // fe_iou (M=16352,N=1536) + ff (M=8160,N=512) in one launch
    front_k<<<1536 + 256, 256, SMEM_TOT>>>(b_fe_iou, b_fe_f);

    leafpair_k<<<(B_ * 128 * F_) / 256, 256>>>();

    for (int n = 1; n <= 8; n++) {
        int np = 1 << (8 - n);
        int s = np - 1;
        int Mf = B_ * 2 * np;
        int Mi = B_ * np;
        int yF = (Mf + 127) / 128;
        int yI = (Mi + 127) / 128;
        level_k<<<4 * yF + 12 * yI, 256, SMEM_TOT>>>(s, np, yF, Mf, Mi);
        if (np > 1) {
            int total = B_ * (np >> 1) * F_;
            gatepair_k<<<(total + 255) / 256, 256>>>(s, np, total);
        } else {
            gateroot_k<<<(B_ * F_) / 256, 256>>>();
        }
    }

    rscore_k<<<2044, 256>>>();
    final_k<<<dim3(4, B_), 128>>>(out);
}

// round 10
// speedup vs baseline: 6.1036x; 1.0543x over previous
#include <cuda_runtime.h>
#include <cuda_fp16.h>
#include <math.h>
#include <cstdint>

#define B_ 32
#define NN 511
#define F_ 512
#define F3 1536

// ======================= scratch (static device globals) =======================
static __device__ __align__(16) float g_enode[B_ * F_];
static __device__ __align__(16) float g_eforw[B_ * F_];
static __device__ __align__(16) float g_scores[B_ * 512];
static __device__ __align__(16) float g_fe_iou[(size_t)B_ * NN * F3];
static __device__ __align__(16) float g_ff[(size_t)B_ * 255 * F_];
static __device__ __align__(16) float g_h[(size_t)B_ * NN * F_];
static __device__ __align__(16) float g_c[(size_t)B_ * NN * F_];
static __device__ __align__(16) float g_fc[(size_t)B_ * 256 * F_];
static __device__ __align__(16) float g_iou[(size_t)B_ * 128 * F3];
static __device__ __align__(16) float g_r[B_ * 512];
// fp16 activations (single precision-rounded copy)
static __device__ __align__(16) __half g_f2[(size_t)B_ * NN * F_];
static __device__ __align__(16) __half g_ha[(size_t)B_ * NN * F_];
static __device__ __align__(16) __half g_hs[(size_t)B_ * 128 * F_];
// fp16 hi/lo weights
static __device__ __align__(16) __half g_wfeiou_h[F3 * F_], g_wfeiou_l[F3 * F_];
static __device__ __align__(16) __half g_wfef_h[F_ * F_],  g_wfef_l[F_ * F_];
static __device__ __align__(16) __half g_wf_h[F_ * F_],    g_wf_l[F_ * F_];
static __device__ __align__(16) __half g_wiou_h[F3 * F_],  g_wiou_l[F3 * F_];

__device__ __forceinline__ float sigf(float x) { return 1.f / (1.f + expf(-x)); }
__device__ __forceinline__ void split_h(float x, __half& h, __half& l) {
    h = __float2half(x);
    l = __float2half(x - __half2float(h));
}

__device__ __forceinline__ uint32_t smem_u32(const void* p) {
    uint32_t a;
    asm("{ .reg .u64 t; cvta.to.shared.u64 t, %1; cvt.u32.u64 %0, t; }" : "=r"(a) : "l"(p));
    return a;
}

#define CP16(dst, src) \
    asm volatile("cp.async.cg.shared.global [%0], [%1], 16;" :: "r"(dst), "l"(src) : "memory")
#define CP_COMMIT() asm volatile("cp.async.commit_group;" ::: "memory")
template <int N>
__device__ __forceinline__ void cp_wait() {
    asm volatile("cp.async.wait_group %0;" :: "n"(N) : "memory");
}

__device__ __forceinline__ void mma16816(float* c, const uint32_t* a, const uint32_t* b) {
    asm volatile(
        "mma.sync.aligned.m16n8k16.row.col.f32.f16.f16.f32 "
        "{%0,%1,%2,%3}, {%4,%5,%6,%7}, {%8,%9}, {%0,%1,%2,%3};"
        : "+f"(c[0]), "+f"(c[1]), "+f"(c[2]), "+f"(c[3])
        : "r"(a[0]), "r"(a[1]), "r"(a[2]), "r"(a[3]), "r"(b[0]), "r"(b[1]));
}

__device__ __forceinline__ void ldsm4(uint32_t& r0, uint32_t& r1, uint32_t& r2, uint32_t& r3,
                                      uint32_t addr) {
    asm volatile("ldmatrix.sync.aligned.m8n8.x4.shared.b16 {%0,%1,%2,%3}, [%4];"
                 : "=r"(r0), "=r"(r1), "=r"(r2), "=r"(r3) : "r"(addr));
}

// ======================= prologue (weight conversion + enode/eforw fused) =======================
__global__ void prolog_k(const float* __restrict__ s0, const float* __restrict__ s1,
                         const float* __restrict__ s2, const float* __restrict__ s3,
                         const float* __restrict__ eh, const float* __restrict__ Wn,
                         const float* __restrict__ Wf) {
    int bx = blockIdx.x;
    if (bx < 8192) {
        int i = bx * 256 + threadIdx.x;  // total 2097152
        if (i < 786432) {
            split_h(s0[i], g_wfeiou_h[i], g_wfeiou_l[i]);
        } else if (i < 1048576) {
            int j = i - 786432;
            split_h(s1[j], g_wfef_h[j], g_wfef_l[j]);
        } else if (i < 1310720) {
            int j = i - 1048576;
            split_h(s2[j], g_wf_h[j], g_wf_l[j]);
        } else {
            int j = i - 1310720;
            split_h(s3[j], g_wiou_h[j], g_wiou_l[j]);
        }
    } else {
        bx -= 8192;                       // 4096 blocks: x(64) | b(32) | z(2)
        int x = bx & 63, b = (bx >> 6) & 31, z = bx >> 11;
        int warp = threadIdx.x >> 5, lane = threadIdx.x & 31;
        int j = x * 8 + warp;
        const float* W = z ? Wf : Wn;
        float* o = z ? g_eforw : g_enode;
        const float4* wr = (const float4*)(W + (size_t)j * 1024);
        const float4* er = (const float4*)(eh + (size_t)b * 1024);
        float s = 0.f;
        for (int t = lane; t < 256; t += 32) {
            float4 w = wr[t], e = er[t];
            s += w.x * e.x + w.y * e.y + w.z * e.z + w.w * e.w;
        }
        #pragma unroll
        for (int off = 16; off; off >>= 1) s += __shfl_xor_sync(0xffffffffu, s, off);
        if (!lane) o[b * F_ + j] = s;
    }
}

__global__ void scores_k(const float* __restrict__ feat) {
    int gw = (blockIdx.x * blockDim.x + threadIdx.x) >> 5;
    int lane = threadIdx.x & 31;
    if (gw >= B_ * NN) return;
    int b = gw / NN;
    const float4* fr = (const float4*)(feat + (size_t)gw * F_);
    const float4* er = (const float4*)(g_enode + b * F_);
    float s = 0.f;
    for (int t = lane; t < 128; t += 32) {
        float4 f = fr[t], e = er[t];
        s += f.x * e.x + f.y * e.y + f.z * e.z + f.w * e.w;
    }
    #pragma unroll
    for (int off = 16; off; off >>= 1) s += __shfl_xor_sync(0xffffffffu, s, off);
    if (!lane) g_scores[b * 512 + (gw - b * NN)] = s;
}

// ---------------- streaming feat2: rolling 4-row window ----------------
__global__ void __launch_bounds__(128)
feat2_k(const float* __restrict__ feat) {
    __shared__ float pr[64][4];
    const int ic = blockIdx.x, b = blockIdx.y, fch = blockIdx.z;
    const int tid = threadIdx.x;
    const int start = ic * 64;

    if (tid < 64) {
        int i = start + tid;
        if (i < NN) {
            int cnt = min(i + 3, NN - 1) - i + 1;
            float sc[4], mx = -1e30f;
            #pragma unroll
            for (int k = 0; k < 4; k++) {
                sc[k] = (k < cnt) ? g_scores[b * 512 + i + k] : -1e30f;
                mx = fmaxf(mx, sc[k]);
            }
            float sum = 0.f;
            #pragma unroll
            for (int k = 0; k < 4; k++) {
                sc[k] = (k < cnt) ? expf(sc[k] - mx) : 0.f;
                sum += sc[k];
            }
            float inv = 1.f / sum;
            #pragma unroll
            for (int k = 0; k < 4; k++) pr[tid][k] = sc[k] * inv;
        }
    }
    __syncthreads();

    const int f = fch * 128 + tid;
    const float* fb = feat + ((size_t)b * NN) * F_ + f;
    float r0 = fb[(size_t)min(start, NN - 1) * F_];
    float r1 = fb[(size_t)min(start + 1, NN - 1) * F_];
    float r2 = fb[(size_t)min(start + 2, NN - 1) * F_];
    size_t obase = ((size_t)b * NN + start) * F_ + f;
    const int nout = min(64, NN - start);
    for (int j = 0; j < nout; j++) {
        int i = start + j;
        float r3 = fb[(size_t)min(i + 3, NN - 1) * F_];
        float a = pr[j][0] * r0 + pr[j][1] * r1 + pr[j][2] * r2 + pr[j][3] * r3;
        g_f2[obase] = __float2half(a);
        obase += F_;
        r0 = r1; r1 = r2; r2 = r3;
    }
}

// ======================= HMMA GEMM core (fp16, fp32 acc) =======================
// Block tile 128x128x32, 8 warps (2M x 4N), warp tile 64x32, ldmatrix fragments.
// 3-stage cp.async pipeline, single __syncthreads per chunk.
// MODE 0: fe_iou = feat2 @ W_fe_iou^T + bias          (2-pass W hi/lo)
// MODE 1: ff     = feat2[parents] @ W_fe_f^T + bias   (1-pass, sigmoid-damped)
// MODE 2: fc     = sigmoid(h[child] @ W_f^T + ff[parent]) * c[child]  (1-pass)
// MODE 3: iou    = hsum @ W_iou^T + fe_iou[parent]    (2-pass W hi/lo)
#define TILE_B 10240
#define STAGE_B (3 * TILE_B)
#define SMEM_TOT (3 * STAGE_B)

template <int MODE>
__device__ __forceinline__ void gemm_core(char* smem, int bm, int bn,
                                          const float* __restrict__ bias,
                                          int M, int s, int np) {
    constexpr bool TP = (MODE == 0 || MODE == 3);   // two-pass weights
    const uint32_t sb = smem_u32(smem);
    const int tid = threadIdx.x;
    const int warp = tid >> 5, lane = tid & 31;
    const int wm = warp >> 2, wn = warp & 3;
    const int qrow = lane >> 2, qcol = (lane & 3) * 2;

    const __half *Aa, *Wh, *Wl;
    if (MODE == 0) { Aa = g_f2; Wh = g_wfeiou_h; Wl = g_wfeiou_l; }
    else if (MODE == 1) { Aa = g_f2; Wh = g_wfef_h; Wl = g_wfef_l; }
    else if (MODE == 2) { Aa = g_ha; Wh = g_wf_h; Wl = g_wf_l; }
    else { Aa = g_hs; Wh = g_wiou_h; Wl = g_wiou_l; }

    // --- cp.async geometry: each thread covers 2 rows (row0, row0+64), one 16B quad ---
    const int quad = tid & 3;
    const int row0 = tid >> 2;
    int ar0, ar1;
    {
        int rA = min(bm + row0, M - 1);
        int rB = min(bm + row0 + 64, M - 1);
        if (MODE == 0 || MODE == 3) { ar0 = rA; ar1 = rB; }
        else if (MODE == 1) {
            int b0 = rA / 255; ar0 = b0 * NN + (rA - b0 * 255);
            int b1 = rB / 255; ar1 = b1 * NN + (rB - b1 * 255);
        } else {
            int two = 2 * np;
            int b0 = rA / two; ar0 = b0 * NN + 2 * s + 1 + (rA - b0 * two);
            int b1 = rB / two; ar1 = b1 * NN + 2 * s + 1 + (rB - b1 * two);
        }
    }
    const int a00 = ar0 * F_ + quad * 8;
    const int a01 = ar1 * F_ + quad * 8;
    const int w00 = (bn + row0) * F_ + quad * 8;
    const int w01 = (bn + row0 + 64) * F_ + quad * 8;
    const uint32_t d0 = (uint32_t)(row0 * 80 + quad * 16);
    const uint32_t d1 = d0 + 64 * 80;

    // --- ldmatrix lane offsets ---
    const uint32_t a_l = (uint32_t)((wm * 64 + (lane & 15)) * 80 + (lane >> 4) * 16);
    const uint32_t b_l = (uint32_t)((wn * 32 + ((lane >> 4) & 1) * 8 + (lane & 7)) * 80 +
                                    ((lane >> 3) & 1) * 16);

#define LOAD_CHUNK(cidx, stgi) do {                                        \
    int k0 = (cidx) * 32;                                                  \
    uint32_t s0a = sb + (stgi) * STAGE_B;                                  \
    CP16(s0a + d0,              Aa + a00 + k0);                            \
    CP16(s0a + d1,              Aa + a01 + k0);                            \
    CP16(s0a + TILE_B + d0,     Wh + w00 + k0);                            \
    CP16(s0a + TILE_B + d1,     Wh + w01 + k0);                            \
    if (TP) {                                                              \
        CP16(s0a + 2 * TILE_B + d0, Wl + w00 + k0);                        \
        CP16(s0a + 2 * TILE_B + d1, Wl + w01 + k0);                        \
    }                                                                      \
    CP_COMMIT();                                                          \
} while (0)

    float acc[4][4][4] = {};

    LOAD_CHUNK(0, 0);
    LOAD_CHUNK(1, 1);

    int stg_idx = 0;
    for (int c = 0; c < 16; c++) {
        if (c < 15) cp_wait<1>(); else cp_wait<0>();
        __syncthreads();
        if (c < 14) {
            int ns = stg_idx + 2; if (ns >= 3) ns -= 3;
            LOAD_CHUNK(c + 2, ns);
        }

        const uint32_t stg = sb + stg_idx * STAGE_B;
        #pragma unroll
        for (int kk = 0; kk < 2; kk++) {
            uint32_t ah[4][4], bh[2][4], bl[2][4];
            #pragma unroll
            for (int mf = 0; mf < 4; mf++) {
                ldsm4(ah[mf][0], ah[mf][1], ah[mf][2], ah[mf][3],
                      stg + a_l + mf * 1280 + kk * 32);
            }
            #pragma unroll
            for (int p = 0; p < 2; p++) {
                uint32_t baddr = stg + TILE_B + b_l + p * 1280 + kk * 32;
                ldsm4(bh[p][0], bh[p][1], bh[p][2], bh[p][3], baddr);
                if (TP) ldsm4(bl[p][0], bl[p][1], bl[p][2], bl[p][3], baddr + TILE_B);
            }
            #pragma unroll
            for (int mf = 0; mf < 4; mf++)
                #pragma unroll
                for (int p = 0; p < 2; p++)
                    #pragma unroll
                    for (int q = 0; q < 2; q++) {
                        int nf = p * 2 + q;
                        mma16816(acc[mf][nf], ah[mf], &bh[p][2 * q]);
                        if (TP) mma16816(acc[mf][nf], ah[mf], &bl[p][2 * q]);
                    }
        }
        if (++stg_idx == 3) stg_idx = 0;
    }
#undef LOAD_CHUNK

    // --- epilogue ---
    #pragma unroll
    for (int mf = 0; mf < 4; mf++) {
        #pragma unroll
        for (int half = 0; half < 2; half++) {
            int m = bm + wm * 64 + mf * 16 + qrow + half * 8;
            if (m >= M) continue;
            int b = 0, node = 0, p = 0;
            if (MODE == 2) {
                int two = 2 * np;
                b = m / two;
                int cl = m - b * two;
                node = 2 * s + 1 + cl;
                p = s + (cl >> 1);
            } else if (MODE == 3) {
                b = m / np;
                p = s + (m - b * np);
            }
            #pragma unroll
            for (int nf = 0; nf < 4; nf++) {
                int n = bn + wn * 32 + nf * 8 + qcol;
                float2 v = make_float2(acc[mf][nf][half * 2], acc[mf][nf][half * 2 + 1]);
                if (MODE == 0) {
                    float2 bi = *(const float2*)(bias + n);
                    v.x += bi.x; v.y += bi.y;
                    *(float2*)(g_fe_iou + (size_t)m * F3 + n) = v;
                } else if (MODE == 1) {
                    float2 bi = *(const float2*)(bias + n);
                    v.x += bi.x; v.y += bi.y;
                    *(float2*)(g_ff + (size_t)m * F_ + n) = v;
                } else if (MODE == 2) {
                    float2 ffv = *(const float2*)(g_ff + ((size_t)b * 255 + p) * F_ + n);
                    float2 cv  = *(const float2*)(g_c + ((size_t)b * NN + node) * F_ + n);
                    float2 o;
                    o.x = sigf(v.x + ffv.x) * cv.x;
                    o.y = sigf(v.y + ffv.y) * cv.y;
                    *(float2*)(g_fc + (size_t)m * F_ + n) = o;
                } else {
                    float2 fe = *(const float2*)(g_fe_iou + ((size_t)b * NN + p) * F3 + n);
                    v.x += fe.x; v.y += fe.y;
                    *(float2*)(g_iou + (size_t)m * F3 + n) = v;
                }
            }
        }
    }
}

// combined front GEMMs: fe_iou (12-wide tiles) then ff (4-wide tiles)
__global__ void __launch_bounds__(256, 2)
front_k(const float* __restrict__ b_iou, const float* __restrict__ b_f) {
    extern __shared__ char smem[];
    int bx = blockIdx.x;
    if (bx < 1536) {
        gemm_core<0>(smem, (bx / 12) * 128, (bx % 12) * 128, b_iou, 16352, 0, 0);
    } else {
        bx -= 1536;
        gemm_core<1>(smem, (bx >> 2) * 128, (bx & 3) * 128, b_f, 8160, 0, 0);
    }
}

// fused per-level kernel: fc blocks first, iou blocks after
__global__ void __launch_bounds__(256, 2)
level_k(int s, int np, int yF, int Mf, int Mi) {
    extern __shared__ char smem[];
    int bx = blockIdx.x;
    if (bx < 4 * yF) {
        gemm_core<2>(smem, (bx >> 2) * 128, (bx & 3) * 128, nullptr, Mf, s, np);
    } else {
        bx -= 4 * yF;
        gemm_core<3>(smem, (bx / 12) * 128, (bx % 12) * 128, nullptr, Mi, s, np);
    }
}

// ======================= gates (pair-fused with hsum) =======================
__global__ void leafpair_k() {
    int idx = blockIdx.x * blockDim.x + threadIdx.x;  // 32*128*512
    int f = idx & 511, r = idx >> 9;   // r = b*128 + j
    int b = r >> 7, j = r & 127;
    float hs = 0.f;
    #pragma unroll
    for (int t = 0; t < 2; t++) {
        int node = 255 + 2 * j + t;
        size_t io = ((size_t)b * NN + node) * F3;
        float cn = sigf(g_fe_iou[io + f]) * fmaxf(g_fe_iou[io + 1024 + f], 0.f);
        float hn = sigf(g_fe_iou[io + 512 + f]) * tanhf(cn);
        size_t ho = ((size_t)b * NN + node) * F_ + f;
        g_c[ho] = cn;
        g_h[ho] = hn;
        g_ha[ho] = __float2half(hn);
        hs += hn;
    }
    g_hs[(size_t)r * F_ + f] = __float2half(hs);
}

__global__ void gatepair_k(int s, int np, int total) {
    int idx = blockIdx.x * blockDim.x + threadIdx.x;
    if (idx >= total) return;
    int f = idx & 511, r = idx >> 9;   // r = b*half + j
    int half = np >> 1;
    int b = r / half, j = r - b * half;
    float hs = 0.f;
    #pragma unroll
    for (int t = 0; t < 2; t++) {
        int pl = 2 * j + t;
        int rr = b * np + pl;
        int node = s + pl;
        size_t io = (size_t)rr * F3;
        float csum = g_fc[(size_t)(2 * rr) * F_ + f] + g_fc[(size_t)(2 * rr + 1) * F_ + f];
        float cn = sigf(g_iou[io + f]) * fmaxf(g_iou[io + 1024 + f], 0.f) + csum;
        float hn = sigf(g_iou[io + 512 + f]) * tanhf(cn);
        size_t ho = ((size_t)b * NN + node) * F_ + f;
        g_c[ho] = cn;
        g_h[ho] = hn;
        g_ha[ho] = __float2half(hn);
        hs += hn;
    }
    g_hs[(size_t)r * F_ + f] = __float2half(hs);
}

// ======================= readout (root gate fused into rscore) =======================
__global__ void rscore_k() {
    int gw = (blockIdx.x * blockDim.x + threadIdx.x) >> 5;
    int lane = threadIdx.x & 31;
    if (gw >= B_ * NN) return;
    int b = gw / NN;
    int i = gw - b * NN;
    float s = 0.f;
    if (i == 0) {
        // root gate: level 8 left g_iou rows r=b (np=1) and g_fc rows 2b, 2b+1
        size_t io = (size_t)b * F3;
        for (int f = lane; f < F_; f += 32) {
            float csum = g_fc[(size_t)(2 * b) * F_ + f] + g_fc[(size_t)(2 * b + 1) * F_ + f];
            float cn = sigf(g_iou[io + f]) * fmaxf(g_iou[io + 1024 + f], 0.f) + csum;
            float hn = sigf(g_iou[io + 512 + f]) * tanhf(cn);
            g_h[(size_t)b * NN * F_ + f] = hn;   // node 0 row, read by final_k
            s += hn * g_eforw[b * F_ + f];
        }
    } else {
        const float4* hp = (const float4*)(g_h + (size_t)gw * F_);
        const float4* ep = (const float4*)(g_eforw + b * F_);
        for (int t = lane; t < 128; t += 32) {
            float4 h = hp[t], e = ep[t];
            s += h.x * e.x + h.y * e.y + h.z * e.z + h.w * e.w;
        }
    }
    #pragma unroll
    for (int off = 16; off; off >>= 1) s += __shfl_xor_sync(0xffffffffu, s, off);
    if (!lane) g_r[b * 512 + i] = s;
}

__global__ void final_k(float* __restrict__ out) {
    __shared__ float red[128];
    __shared__ float pr[NN];
    int b = blockIdx.y, tid = threadIdx.x;
    float mx = -1e30f;
    for (int i = tid; i < NN; i += 128) mx = fmaxf(mx, g_r[b * 512 + i]);
    red[tid] = mx;
    __syncthreads();
    for (int o = 64; o; o >>= 1) {
        if (tid < o) red[tid] = fmaxf(red[tid], red[tid + o]);
        __syncthreads();
    }
    mx = red[0];
    __syncthreads();
    float sm = 0.f;
    for (int i = tid; i < NN; i += 128) {
        float e = expf(g_r[b * 512 + i] - mx);
        pr[i] = e;
        sm += e;
    }
    red[tid] = sm;
    __syncthreads();
    for (int o = 64; o; o >>= 1) {
        if (tid < o) red[tid] += red[tid + o];
        __syncthreads();
    }
    float inv = 1.f / red[0];
    __syncthreads();
    int f = blockIdx.x * 128 + tid;
    float acc = 0.f;
    for (int i = 0; i < NN; i++) acc += pr[i] * g_h[((size_t)b * NN + i) * F_ + f];
    out[b * F_ + f] = acc * inv;
}

// ======================= launcher =======================
extern "C" void kernel_launch(void* const* d_in, const int* in_sizes, int n_in,
                              void* d_out, int out_size) {
    const float* feat     = (const float*)d_in[0];
    const float* eh       = (const float*)d_in[5];
    const float* Wn       = (const float*)d_in[6];
    const float* Wf       = (const float*)d_in[7];
    const float* W_iou    = (const float*)d_in[8];
    const float* W_fe_iou = (const float*)d_in[9];
    const float* b_fe_iou = (const float*)d_in[10];
    const float* W_f      = (const float*)d_in[11];
    const float* W_fe_f   = (const float*)d_in[12];
    const float* b_fe_f   = (const float*)d_in[13];
    float* out = (float*)d_out;

    static bool attr_done = false;
    if (!attr_done) {
        cudaFuncSetAttribute(front_k, cudaFuncAttributeMaxDynamicSharedMemorySize, SMEM_TOT);
        cudaFuncSetAttribute(level_k, cudaFuncAttributeMaxDynamicSharedMemorySize, SMEM_TOT);
        attr_done = true;
    }

    prolog_k<<<8192 + 4096, 256>>>(W_fe_iou, W_fe_f, W_f, W_iou, eh, Wn, Wf);
    scores_k<<<2044, 256>>>(feat);
    feat2_k<<<dim3(8, B_, 4), 128>>>(feat);

    // fe_iou (M=16352,N=1536) + ff (M=8160,N=512) in one launch
    front_k<<<1536 + 256, 256, SMEM_TOT>>>(b_fe_iou, b_fe_f);

    leafpair_k<<<(B_ * 128 * F_) / 256, 256>>>();

    for (int n = 1; n <= 8; n++) {
        int np = 1 << (8 - n);
        int s = np - 1;
        int Mf = B_ * 2 * np;
        int Mi = B_ * np;
        int yF = (Mf + 127) / 128;
        int yI = (Mi + 127) / 128;
        level_k<<<4 * yF + 12 * yI, 256, SMEM_TOT>>>(s, np, yF, Mf, Mi);
        if (np > 1) {
            int total = B_ * (np >> 1) * F_;
            gatepair_k<<<(total + 255) / 256, 256>>>(s, np, total);
        }
        // np == 1: root gate is fused into rscore_k below
    }

    rscore_k<<<2044, 256>>>();
    final_k<<<dim3(4, B_), 128>>>(out);
}

// round 11
// speedup vs baseline: 6.5561x; 1.0741x over previous
#include <cuda_runtime.h>
#include <cuda_fp16.h>
#include <math.h>
#include <cstdint>

#define B_ 32
#define NN 511
#define F_ 512
#define F3 1536

// ======================= scratch (static device globals) =======================
static __device__ __align__(16) float g_enode[B_ * F_];
static __device__ __align__(16) float g_eforw[B_ * F_];
static __device__ __align__(16) float g_scores[B_ * 512];
static __device__ __align__(16) float g_fe_iou[(size_t)B_ * NN * F3];
static __device__ __align__(16) float g_ff[(size_t)B_ * 255 * F_];
static __device__ __align__(16) float g_h[(size_t)B_ * NN * F_];
static __device__ __align__(16) float g_c[(size_t)B_ * NN * F_];
static __device__ __align__(16) float g_fc[(size_t)B_ * 256 * F_];
static __device__ __align__(16) float g_iou[(size_t)B_ * 128 * F3];
static __device__ __align__(16) float g_r[B_ * 512];
// fp16 activations (single precision-rounded copy)
static __device__ __align__(16) __half g_f2[(size_t)B_ * NN * F_];
static __device__ __align__(16) __half g_ha[(size_t)B_ * NN * F_];
static __device__ __align__(16) __half g_hs[(size_t)B_ * 128 * F_];
// fp16 hi/lo weights
static __device__ __align__(16) __half g_wfeiou_h[F3 * F_], g_wfeiou_l[F3 * F_];
static __device__ __align__(16) __half g_wfef_h[F_ * F_],  g_wfef_l[F_ * F_];
static __device__ __align__(16) __half g_wf_h[F_ * F_],    g_wf_l[F_ * F_];
static __device__ __align__(16) __half g_wiou_h[F3 * F_],  g_wiou_l[F3 * F_];

__device__ __forceinline__ float sigf(float x) { return 1.f / (1.f + expf(-x)); }
__device__ __forceinline__ void split_h(float x, __half& h, __half& l) {
    h = __float2half(x);
    l = __float2half(x - __half2float(h));
}

__device__ __forceinline__ uint32_t smem_u32(const void* p) {
    uint32_t a;
    asm("{ .reg .u64 t; cvta.to.shared.u64 t, %1; cvt.u32.u64 %0, t; }" : "=r"(a) : "l"(p));
    return a;
}

#define CP16(dst, src) \
    asm volatile("cp.async.cg.shared.global [%0], [%1], 16;" :: "r"(dst), "l"(src) : "memory")
#define CP_COMMIT() asm volatile("cp.async.commit_group;" ::: "memory")
template <int N>
__device__ __forceinline__ void cp_wait() {
    asm volatile("cp.async.wait_group %0;" :: "n"(N) : "memory");
}

__device__ __forceinline__ void mma16816(float* c, const uint32_t* a, const uint32_t* b) {
    asm volatile(
        "mma.sync.aligned.m16n8k16.row.col.f32.f16.f16.f32 "
        "{%0,%1,%2,%3}, {%4,%5,%6,%7}, {%8,%9}, {%0,%1,%2,%3};"
        : "+f"(c[0]), "+f"(c[1]), "+f"(c[2]), "+f"(c[3])
        : "r"(a[0]), "r"(a[1]), "r"(a[2]), "r"(a[3]), "r"(b[0]), "r"(b[1]));
}

__device__ __forceinline__ void ldsm4(uint32_t& r0, uint32_t& r1, uint32_t& r2, uint32_t& r3,
                                      uint32_t addr) {
    asm volatile("ldmatrix.sync.aligned.m8n8.x4.shared.b16 {%0,%1,%2,%3}, [%4];"
                 : "=r"(r0), "=r"(r1), "=r"(r2), "=r"(r3) : "r"(addr));
}

// ======================= prologue (weight conversion + enode/eforw fused) =======================
__global__ void prolog_k(const float* __restrict__ s0, const float* __restrict__ s1,
                         const float* __restrict__ s2, const float* __restrict__ s3,
                         const float* __restrict__ eh, const float* __restrict__ Wn,
                         const float* __restrict__ Wf) {
    int bx = blockIdx.x;
    if (bx < 8192) {
        int i = bx * 256 + threadIdx.x;  // total 2097152
        if (i < 786432) {
            split_h(s0[i], g_wfeiou_h[i], g_wfeiou_l[i]);
        } else if (i < 1048576) {
            int j = i - 786432;
            split_h(s1[j], g_wfef_h[j], g_wfef_l[j]);
        } else if (i < 1310720) {
            int j = i - 1048576;
            split_h(s2[j], g_wf_h[j], g_wf_l[j]);
        } else {
            int j = i - 1310720;
            split_h(s3[j], g_wiou_h[j], g_wiou_l[j]);
        }
    } else {
        bx -= 8192;                       // 4096 blocks: x(64) | b(32) | z(2)
        int x = bx & 63, b = (bx >> 6) & 31, z = bx >> 11;
        int warp = threadIdx.x >> 5, lane = threadIdx.x & 31;
        int j = x * 8 + warp;
        const float* W = z ? Wf : Wn;
        float* o = z ? g_eforw : g_enode;
        const float4* wr = (const float4*)(W + (size_t)j * 1024);
        const float4* er = (const float4*)(eh + (size_t)b * 1024);
        float s = 0.f;
        for (int t = lane; t < 256; t += 32) {
            float4 w = wr[t], e = er[t];
            s += w.x * e.x + w.y * e.y + w.z * e.z + w.w * e.w;
        }
        #pragma unroll
        for (int off = 16; off; off >>= 1) s += __shfl_xor_sync(0xffffffffu, s, off);
        if (!lane) o[b * F_ + j] = s;
    }
}

__global__ void scores_k(const float* __restrict__ feat) {
    int gw = (blockIdx.x * blockDim.x + threadIdx.x) >> 5;
    int lane = threadIdx.x & 31;
    if (gw >= B_ * NN) return;
    int b = gw / NN;
    const float4* fr = (const float4*)(feat + (size_t)gw * F_);
    const float4* er = (const float4*)(g_enode + b * F_);
    float s = 0.f;
    for (int t = lane; t < 128; t += 32) {
        float4 f = fr[t], e = er[t];
        s += f.x * e.x + f.y * e.y + f.z * e.z + f.w * e.w;
    }
    #pragma unroll
    for (int off = 16; off; off >>= 1) s += __shfl_xor_sync(0xffffffffu, s, off);
    if (!lane) g_scores[b * 512 + (gw - b * NN)] = s;
}

// ---------------- streaming feat2: rolling 4-row window ----------------
__global__ void __launch_bounds__(128)
feat2_k(const float* __restrict__ feat) {
    __shared__ float pr[64][4];
    const int ic = blockIdx.x, b = blockIdx.y, fch = blockIdx.z;
    const int tid = threadIdx.x;
    const int start = ic * 64;

    if (tid < 64) {
        int i = start + tid;
        if (i < NN) {
            int cnt = min(i + 3, NN - 1) - i + 1;
            float sc[4], mx = -1e30f;
            #pragma unroll
            for (int k = 0; k < 4; k++) {
                sc[k] = (k < cnt) ? g_scores[b * 512 + i + k] : -1e30f;
                mx = fmaxf(mx, sc[k]);
            }
            float sum = 0.f;
            #pragma unroll
            for (int k = 0; k < 4; k++) {
                sc[k] = (k < cnt) ? expf(sc[k] - mx) : 0.f;
                sum += sc[k];
            }
            float inv = 1.f / sum;
            #pragma unroll
            for (int k = 0; k < 4; k++) pr[tid][k] = sc[k] * inv;
        }
    }
    __syncthreads();

    const int f = fch * 128 + tid;
    const float* fb = feat + ((size_t)b * NN) * F_ + f;
    float r0 = fb[(size_t)min(start, NN - 1) * F_];
    float r1 = fb[(size_t)min(start + 1, NN - 1) * F_];
    float r2 = fb[(size_t)min(start + 2, NN - 1) * F_];
    size_t obase = ((size_t)b * NN + start) * F_ + f;
    const int nout = min(64, NN - start);
    for (int j = 0; j < nout; j++) {
        int i = start + j;
        float r3 = fb[(size_t)min(i + 3, NN - 1) * F_];
        float a = pr[j][0] * r0 + pr[j][1] * r1 + pr[j][2] * r2 + pr[j][3] * r3;
        g_f2[obase] = __float2half(a);
        obase += F_;
        r0 = r1; r1 = r2; r2 = r3;
    }
}

// ======================= HMMA GEMM core (fp16, fp32 acc, k-chunk 64) =======================
// Block tile 128x128x64, 8 warps (2M x 4N), warp tile 64x32, ldmatrix fragments.
// 2-stage cp.async pipeline (55KB/stage), 2 syncs per chunk, 8 chunks.
// MODE 0: fe_iou = feat2 @ W_fe_iou^T + bias          (2-pass W hi/lo)
// MODE 1: ff     = feat2[parents] @ W_fe_f^T + bias   (1-pass, sigmoid-damped)
// MODE 2: fc     = sigmoid(h[child] @ W_f^T + ff[parent]) * c[child]  (1-pass)
// MODE 3: iou    = hsum @ W_iou^T + fe_iou[parent]    (2-pass W hi/lo)
#define ROWP 144
#define TILE_B (128 * ROWP)          // 18432
#define STAGE_B (3 * TILE_B)         // 55296
#define SMEM_TOT (2 * STAGE_B)       // 110592

template <int MODE>
__device__ __forceinline__ void gemm_core(char* smem, int bm, int bn,
                                          const float* __restrict__ bias,
                                          int M, int s, int np) {
    constexpr bool TP = (MODE == 0 || MODE == 3);   // two-pass weights
    const uint32_t sb = smem_u32(smem);
    const int tid = threadIdx.x;
    const int warp = tid >> 5, lane = tid & 31;
    const int wm = warp >> 2, wn = warp & 3;
    const int qrow = lane >> 2, qcol = (lane & 3) * 2;

    const __half *Aa, *Wh, *Wl;
    if (MODE == 0) { Aa = g_f2; Wh = g_wfeiou_h; Wl = g_wfeiou_l; }
    else if (MODE == 1) { Aa = g_f2; Wh = g_wfef_h; Wl = g_wfef_l; }
    else if (MODE == 2) { Aa = g_ha; Wh = g_wf_h; Wl = g_wf_l; }
    else { Aa = g_hs; Wh = g_wiou_h; Wl = g_wiou_l; }

    // --- cp.async geometry: rows rowb+32j (j=0..3), one 16B group of the 128B row ---
    const int quad = tid & 7;        // 16B group (8 per row)
    const int rowb = tid >> 3;       // 0..31
    int ar[4], wr[4];
    uint32_t dd[4];
    #pragma unroll
    for (int j = 0; j < 4; j++) {
        int r = rowb + j * 32;
        int rA = min(bm + r, M - 1);
        int arow;
        if (MODE == 0 || MODE == 3) arow = rA;
        else if (MODE == 1) { int b0 = rA / 255; arow = b0 * NN + (rA - b0 * 255); }
        else { int two = 2 * np; int b0 = rA / two; arow = b0 * NN + 2 * s + 1 + (rA - b0 * two); }
        ar[j] = arow * F_ + quad * 8;
        wr[j] = (bn + r) * F_ + quad * 8;
        dd[j] = (uint32_t)(r * ROWP + quad * 16);
    }

    // --- ldmatrix lane offsets ---
    const uint32_t a_l = (uint32_t)((wm * 64 + (lane & 15)) * ROWP + (lane >> 4) * 16);
    const uint32_t b_l = (uint32_t)((wn * 32 + ((lane >> 4) & 1) * 8 + (lane & 7)) * ROWP +
                                    ((lane >> 3) & 1) * 16);

#define LOAD_CHUNK(cidx, stgi) do {                                        \
    int k0 = (cidx) * 64;                                                  \
    uint32_t s0a = sb + (stgi) * STAGE_B;                                  \
    CP16(s0a + dd[0], Aa + ar[0] + k0);                                    \
    CP16(s0a + dd[1], Aa + ar[1] + k0);                                    \
    CP16(s0a + dd[2], Aa + ar[2] + k0);                                    \
    CP16(s0a + dd[3], Aa + ar[3] + k0);                                    \
    CP16(s0a + TILE_B + dd[0], Wh + wr[0] + k0);                           \
    CP16(s0a + TILE_B + dd[1], Wh + wr[1] + k0);                           \
    CP16(s0a + TILE_B + dd[2], Wh + wr[2] + k0);                           \
    CP16(s0a + TILE_B + dd[3], Wh + wr[3] + k0);                           \
    if (TP) {                                                              \
        CP16(s0a + 2 * TILE_B + dd[0], Wl + wr[0] + k0);                   \
        CP16(s0a + 2 * TILE_B + dd[1], Wl + wr[1] + k0);                   \
        CP16(s0a + 2 * TILE_B + dd[2], Wl + wr[2] + k0);                   \
        CP16(s0a + 2 * TILE_B + dd[3], Wl + wr[3] + k0);                   \
    }                                                                      \
    CP_COMMIT();                                                          \
} while (0)

    float acc[4][4][4] = {};

    LOAD_CHUNK(0, 0);

    for (int c = 0; c < 8; c++) {
        if (c) __syncthreads();          // prior compute on the stage LOAD will overwrite is done
        if (c < 7) LOAD_CHUNK(c + 1, (c + 1) & 1);
        if (c < 7) cp_wait<1>(); else cp_wait<0>();
        __syncthreads();                 // chunk-c data visible to all threads

        const uint32_t stg = sb + (c & 1) * STAGE_B;
        #pragma unroll
        for (int kk = 0; kk < 4; kk++) {
            uint32_t ah[4][4], bh[2][4], bl[2][4];
            #pragma unroll
            for (int mf = 0; mf < 4; mf++) {
                ldsm4(ah[mf][0], ah[mf][1], ah[mf][2], ah[mf][3],
                      stg + a_l + mf * 2304 + kk * 32);
            }
            #pragma unroll
            for (int p = 0; p < 2; p++) {
                uint32_t baddr = stg + TILE_B + b_l + p * 2304 + kk * 32;
                ldsm4(bh[p][0], bh[p][1], bh[p][2], bh[p][3], baddr);
                if (TP) ldsm4(bl[p][0], bl[p][1], bl[p][2], bl[p][3], baddr + TILE_B);
            }
            #pragma unroll
            for (int mf = 0; mf < 4; mf++)
                #pragma unroll
                for (int p = 0; p < 2; p++)
                    #pragma unroll
                    for (int q = 0; q < 2; q++) {
                        int nf = p * 2 + q;
                        mma16816(acc[mf][nf], ah[mf], &bh[p][2 * q]);
                        if (TP) mma16816(acc[mf][nf], ah[mf], &bl[p][2 * q]);
                    }
        }
    }
#undef LOAD_CHUNK

    // --- epilogue ---
    #pragma unroll
    for (int mf = 0; mf < 4; mf++) {
        #pragma unroll
        for (int half = 0; half < 2; half++) {
            int m = bm + wm * 64 + mf * 16 + qrow + half * 8;
            if (m >= M) continue;
            int b = 0, node = 0, p = 0;
            if (MODE == 2) {
                int two = 2 * np;
                b = m / two;
                int cl = m - b * two;
                node = 2 * s + 1 + cl;
                p = s + (cl >> 1);
            } else if (MODE == 3) {
                b = m / np;
                p = s + (m - b * np);
            }
            #pragma unroll
            for (int nf = 0; nf < 4; nf++) {
                int n = bn + wn * 32 + nf * 8 + qcol;
                float2 v = make_float2(acc[mf][nf][half * 2], acc[mf][nf][half * 2 + 1]);
                if (MODE == 0) {
                    float2 bi = *(const float2*)(bias + n);
                    v.x += bi.x; v.y += bi.y;
                    *(float2*)(g_fe_iou + (size_t)m * F3 + n) = v;
                } else if (MODE == 1) {
                    float2 bi = *(const float2*)(bias + n);
                    v.x += bi.x; v.y += bi.y;
                    *(float2*)(g_ff + (size_t)m * F_ + n) = v;
                } else if (MODE == 2) {
                    float2 ffv = *(const float2*)(g_ff + ((size_t)b * 255 + p) * F_ + n);
                    float2 cv  = *(const float2*)(g_c + ((size_t)b * NN + node) * F_ + n);
                    float2 o;
                    o.x = sigf(v.x + ffv.x) * cv.x;
                    o.y = sigf(v.y + ffv.y) * cv.y;
                    *(float2*)(g_fc + (size_t)m * F_ + n) = o;
                } else {
                    float2 fe = *(const float2*)(g_fe_iou + ((size_t)b * NN + p) * F3 + n);
                    v.x += fe.x; v.y += fe.y;
                    *(float2*)(g_iou + (size_t)m * F3 + n) = v;
                }
            }
        }
    }
}

// combined front GEMMs: fe_iou (12-wide tiles) then ff (4-wide tiles)
__global__ void __launch_bounds__(256, 2)
front_k(const float* __restrict__ b_iou, const float* __restrict__ b_f) {
    extern __shared__ char smem[];
    int bx = blockIdx.x;
    if (bx < 1536) {
        gemm_core<0>(smem, (bx / 12) * 128, (bx % 12) * 128, b_iou, 16352, 0, 0);
    } else {
        bx -= 1536;
        gemm_core<1>(smem, (bx >> 2) * 128, (bx & 3) * 128, b_f, 8160, 0, 0);
    }
}

// fused per-level kernel: fc blocks first, iou blocks after
__global__ void __launch_bounds__(256, 2)
level_k(int s, int np, int yF, int Mf, int Mi) {
    extern __shared__ char smem[];
    int bx = blockIdx.x;
    if (bx < 4 * yF) {
        gemm_core<2>(smem, (bx >> 2) * 128, (bx & 3) * 128, nullptr, Mf, s, np);
    } else {
        bx -= 4 * yF;
        gemm_core<3>(smem, (bx / 12) * 128, (bx % 12) * 128, nullptr, Mi, s, np);
    }
}

// ======================= gates (pair-fused with hsum) =======================
__global__ void leafpair_k() {
    int idx = blockIdx.x * blockDim.x + threadIdx.x;  // 32*128*512
    int f = idx & 511, r = idx >> 9;   // r = b*128 + j
    int b = r >> 7, j = r & 127;
    float hs = 0.f;
    #pragma unroll
    for (int t = 0; t < 2; t++) {
        int node = 255 + 2 * j + t;
        size_t io = ((size_t)b * NN + node) * F3;
        float cn = sigf(g_fe_iou[io + f]) * fmaxf(g_fe_iou[io + 1024 + f], 0.f);
        float hn = sigf(g_fe_iou[io + 512 + f]) * tanhf(cn);
        size_t ho = ((size_t)b * NN + node) * F_ + f;
        g_c[ho] = cn;
        g_h[ho] = hn;
        g_ha[ho] = __float2half(hn);
        hs += hn;
    }
    g_hs[(size_t)r * F_ + f] = __float2half(hs);
}

__global__ void gatepair_k(int s, int np, int total) {
    int idx = blockIdx.x * blockDim.x + threadIdx.x;
    if (idx >= total) return;
    int f = idx & 511, r = idx >> 9;   // r = b*half + j
    int half = np >> 1;
    int b = r / half, j = r - b * half;
    float hs = 0.f;
    #pragma unroll
    for (int t = 0; t < 2; t++) {
        int pl = 2 * j + t;
        int rr = b * np + pl;
        int node = s + pl;
        size_t io = (size_t)rr * F3;
        float csum = g_fc[(size_t)(2 * rr) * F_ + f] + g_fc[(size_t)(2 * rr + 1) * F_ + f];
        float cn = sigf(g_iou[io + f]) * fmaxf(g_iou[io + 1024 + f], 0.f) + csum;
        float hn = sigf(g_iou[io + 512 + f]) * tanhf(cn);
        size_t ho = ((size_t)b * NN + node) * F_ + f;
        g_c[ho] = cn;
        g_h[ho] = hn;
        g_ha[ho] = __float2half(hn);
        hs += hn;
    }
    g_hs[(size_t)r * F_ + f] = __float2half(hs);
}

// ======================= readout (root gate fused into rscore) =======================
__global__ void rscore_k() {
    int gw = (blockIdx.x * blockDim.x + threadIdx.x) >> 5;
    int lane = threadIdx.x & 31;
    if (gw >= B_ * NN) return;
    int b = gw / NN;
    int i = gw - b * NN;
    float s = 0.f;
    if (i == 0) {
        // root gate: level 8 left g_iou rows r=b (np=1) and g_fc rows 2b, 2b+1
        size_t io = (size_t)b * F3;
        for (int f = lane; f < F_; f += 32) {
            float csum = g_fc[(size_t)(2 * b) * F_ + f] + g_fc[(size_t)(2 * b + 1) * F_ + f];
            float cn = sigf(g_iou[io + f]) * fmaxf(g_iou[io + 1024 + f], 0.f) + csum;
            float hn = sigf(g_iou[io + 512 + f]) * tanhf(cn);
            g_h[(size_t)b * NN * F_ + f] = hn;   // node 0 row, read by final_k
            s += hn * g_eforw[b * F_ + f];
        }
    } else {
        const float4* hp = (const float4*)(g_h + (size_t)gw * F_);
        const float4* ep = (const float4*)(g_eforw + b * F_);
        for (int t = lane; t < 128; t += 32) {
            float4 h = hp[t], e = ep[t];
            s += h.x * e.x + h.y * e.y + h.z * e.z + h.w * e.w;
        }
    }
    #pragma unroll
    for (int off = 16; off; off >>= 1) s += __shfl_xor_sync(0xffffffffu, s, off);
    if (!lane) g_r[b * 512 + i] = s;
}

__global__ void final_k(float* __restrict__ out) {
    __shared__ float red[128];
    __shared__ float pr[NN];
    int b = blockIdx.y, tid = threadIdx.x;
    float mx = -1e30f;
    for (int i = tid; i < NN; i += 128) mx = fmaxf(mx, g_r[b * 512 + i]);
    red[tid] = mx;
    __syncthreads();
    for (int o = 64; o; o >>= 1) {
        if (tid < o) red[tid] = fmaxf(red[tid], red[tid + o]);
        __syncthreads();
    }
    mx = red[0];
    __syncthreads();
    float sm = 0.f;
    for (int i = tid; i < NN; i += 128) {
        float e = expf(g_r[b * 512 + i] - mx);
        pr[i] = e;
        sm += e;
    }
    red[tid] = sm;
    __syncthreads();
    for (int o = 64; o; o >>= 1) {
        if (tid < o) red[tid] += red[tid + o];
        __syncthreads();
    }
    float inv = 1.f / red[0];
    __syncthreads();
    int f = blockIdx.x * 128 + tid;
    float acc = 0.f;
    for (int i = 0; i < NN; i++) acc += pr[i] * g_h[((size_t)b * NN + i) * F_ + f];
    out[b * F_ + f] = acc * inv;
}

// ======================= launcher =======================
extern "C" void kernel_launch(void* const* d_in, const int* in_sizes, int n_in,
                              void* d_out, int out_size) {
    const float* feat     = (const float*)d_in[0];
    const float* eh       = (const float*)d_in[5];
    const float* Wn       = (const float*)d_in[6];
    const float* Wf       = (const float*)d_in[7];
    const float* W_iou    = (const float*)d_in[8];
    const float* W_fe_iou = (const float*)d_in[9];
    const float* b_fe_iou = (const float*)d_in[10];
    const float* W_f      = (const float*)d_in[11];
    const float* W_fe_f   = (const float*)d_in[12];
    const float* b_fe_f   = (const float*)d_in[13];
    float* out = (float*)d_out;

    static bool attr_done = false;
    if (!attr_done) {
        cudaFuncSetAttribute(front_k, cudaFuncAttributeMaxDynamicSharedMemorySize, SMEM_TOT);
        cudaFuncSetAttribute(level_k, cudaFuncAttributeMaxDynamicSharedMemorySize, SMEM_TOT);
        attr_done = true;
    }

    prolog_k<<<8192 + 4096, 256>>>(W_fe_iou, W_fe_f, W_f, W_iou, eh, Wn, Wf);
    scores_k<<<2044, 256>>>(feat);
    feat2_k<<<dim3(8, B_, 4), 128>>>(feat);

    // fe_iou (M=16352,N=1536) + ff (M=8160,N=512) in one launch
    front_k<<<1536 + 256, 256, SMEM_TOT>>>(b_fe_iou, b_fe_f);

    leafpair_k<<<(B_ * 128 * F_) / 256, 256>>>();

    for (int n = 1; n <= 8; n++) {
        int np = 1 << (8 - n);
        int s = np - 1;
        int Mf = B_ * 2 * np;
        int Mi = B_ * np;
        int yF = (Mf + 127) / 128;
        int yI = (Mi + 127) / 128;
        level_k<<<4 * yF + 12 * yI, 256, SMEM_TOT>>>(s, np, yF, Mf, Mi);
        if (np > 1) {
            int total = B_ * (np >> 1) * F_;
            gatepair_k<<<(total + 255) / 256, 256>>>(s, np, total);
        }
        // np == 1: root gate is fused into rscore_k below
    }

    rscore_k<<<2044, 256>>>();
    final_k<<<dim3(4, B_), 128>>>(out);
}